// round 1
// baseline (speedup 1.0000x reference)
#include <cuda_runtime.h>
#include <math.h>

#define SEQ 4096
#define DM  1024
#define DK  128
#define BM  16
#define BN  64
#define NTILES_ROW (SEQ / BM)          // 256
#define ATTN_BLOCKS (NTILES_ROW / 2)   // 128 (pairing b with 255-b)

#define KPAD 129
#define VPAD 132
#define PPAD 68

// Scratch for projected Q/K/V (static device memory: allowed; no runtime allocs)
__device__ float g_qp[SEQ * DK];
__device__ float g_kp[SEQ * DK];
__device__ float g_vp[SEQ * DK];

// ---------------------------------------------------------------------------
// Projection: OUT = X @ W + b   (X: [4096,1024], W: [1024,128])
// 256 threads, 32 rows per block, thread tile 4 rows x 4 cols.
// grid = (128, 3): y selects q/k/v.
// ---------------------------------------------------------------------------
__global__ void __launch_bounds__(256) proj_kernel(
    const float* __restrict__ q, const float* __restrict__ k, const float* __restrict__ v,
    const float* __restrict__ Wq, const float* __restrict__ bq,
    const float* __restrict__ Wk, const float* __restrict__ bk,
    const float* __restrict__ Wv, const float* __restrict__ bv)
{
    const int which = blockIdx.y;
    const float* X = (which == 0) ? q  : (which == 1) ? k  : v;
    const float* W = (which == 0) ? Wq : (which == 1) ? Wk : Wv;
    const float* B = (which == 0) ? bq : (which == 1) ? bk : bv;
    float* OUT     = (which == 0) ? g_qp : (which == 1) ? g_kp : g_vp;

    __shared__ float Xs[32 * 33];    // 32 rows x 32 k, pad 33
    __shared__ float Ws[32 * 128];   // 32 k x 128 cols

    const int t    = threadIdx.x;          // 0..255
    const int rowg = t >> 5;               // 0..7  -> rows rowg*4..+3
    const int colg = t & 31;               // 0..31 -> cols colg*4..+3
    const int r0   = blockIdx.x * 32;

    float acc[4][4];
#pragma unroll
    for (int i = 0; i < 4; i++)
#pragma unroll
        for (int j = 0; j < 4; j++) acc[i][j] = 0.f;

    for (int k0 = 0; k0 < DM; k0 += 32) {
        __syncthreads();
        // stage X chunk: 32x32 floats, 4 per thread, coalesced
#pragma unroll
        for (int i = 0; i < 4; i++) {
            int idx = t + i * 256;
            int rr = idx >> 5, kk = idx & 31;
            Xs[rr * 33 + kk] = X[(r0 + rr) * DM + k0 + kk];
        }
        // stage W chunk: 32x128 floats = 1024 float4, 4 per thread, coalesced
#pragma unroll
        for (int i = 0; i < 4; i++) {
            int idx4 = t + i * 256;
            int rr = idx4 >> 5, c4 = idx4 & 31;
            float4 w = *reinterpret_cast<const float4*>(&W[(k0 + rr) * DK + c4 * 4]);
            *reinterpret_cast<float4*>(&Ws[rr * DK + c4 * 4]) = w;
        }
        __syncthreads();

#pragma unroll 4
        for (int kk = 0; kk < 32; kk++) {
            float x0 = Xs[(rowg * 4 + 0) * 33 + kk];
            float x1 = Xs[(rowg * 4 + 1) * 33 + kk];
            float x2 = Xs[(rowg * 4 + 2) * 33 + kk];
            float x3 = Xs[(rowg * 4 + 3) * 33 + kk];
            float4 w = *reinterpret_cast<const float4*>(&Ws[kk * DK + colg * 4]);
            acc[0][0] += x0 * w.x; acc[0][1] += x0 * w.y; acc[0][2] += x0 * w.z; acc[0][3] += x0 * w.w;
            acc[1][0] += x1 * w.x; acc[1][1] += x1 * w.y; acc[1][2] += x1 * w.z; acc[1][3] += x1 * w.w;
            acc[2][0] += x2 * w.x; acc[2][1] += x2 * w.y; acc[2][2] += x2 * w.z; acc[2][3] += x2 * w.w;
            acc[3][0] += x3 * w.x; acc[3][1] += x3 * w.y; acc[3][2] += x3 * w.z; acc[3][3] += x3 * w.w;
        }
    }

    float4 bias = *reinterpret_cast<const float4*>(&B[colg * 4]);
#pragma unroll
    for (int i = 0; i < 4; i++) {
        int row = r0 + rowg * 4 + i;
        float4 o;
        o.x = acc[i][0] + bias.x; o.y = acc[i][1] + bias.y;
        o.z = acc[i][2] + bias.z; o.w = acc[i][3] + bias.w;
        *reinterpret_cast<float4*>(&OUT[row * DK + colg * 4]) = o;
    }
}

// ---------------------------------------------------------------------------
// Causal flash attention, fp32, online softmax.
// 128 threads. Block b processes row-tiles b and 255-b (load balance).
// S mapping : rowg=t>>4 (2 rows each), colg=t&15, cols c = colg + 16*j (j<4)
//             -> conflict-free K reads (16 consecutive banks).
// PV mapping: rowg same, dg=t&15, d = dg*8 (two float4 V reads per c).
// ---------------------------------------------------------------------------
__global__ void __launch_bounds__(128) attn_kernel(float* __restrict__ out)
{
    extern __shared__ float sm[];
    float* Qs  = sm;                    // 16 x 129
    float* Ks  = Qs + BM * KPAD;        // 64 x 129
    float* Vs  = Ks + BN * KPAD;        // 64 x 132
    float* Ps  = Vs + BN * VPAD;        // 16 x 68
    float* m_s = Ps + BM * PPAD;        // 16
    float* l_s = m_s + BM;              // 16
    float* sc_s = l_s + BM;             // 16

    const int t    = threadIdx.x;
    const int rowg = t >> 4;            // 0..7
    const int colg = t & 15;            // 0..15
    const int r0l  = rowg * 2;          // local row base
    const int dg   = colg;              // PV d-group: d = dg*8
    const float scale = 0.08838834764831845f;   // 1/sqrt(128)

    for (int pass = 0; pass < 2; pass++) {
        const int tileId = (pass == 0) ? (int)blockIdx.x : (NTILES_ROW - 1 - (int)blockIdx.x);
        const int rbase  = tileId * BM;

        if (t < BM) { m_s[t] = -1e30f; l_s[t] = 0.f; }

        // load Q tile [16 x 128]
#pragma unroll
        for (int i = 0; i < 4; i++) {
            int idx = t + i * 128;           // float4 index 0..511
            int rr = idx >> 5, c4 = idx & 31;
            float4 qv = *reinterpret_cast<const float4*>(&g_qp[(rbase + rr) * DK + c4 * 4]);
            float* dst = &Qs[rr * KPAD + c4 * 4];
            dst[0] = qv.x; dst[1] = qv.y; dst[2] = qv.z; dst[3] = qv.w;
        }

        float o0[8], o1[8];
#pragma unroll
        for (int j = 0; j < 8; j++) { o0[j] = 0.f; o1[j] = 0.f; }

        const int ntiles = (rbase + BM - 1) / BN + 1;
        for (int tc = 0; tc < ntiles; tc++) {
            const int c0 = tc * BN;
            __syncthreads();   // protects stats init (tc==0) and smem reuse (tc>0)

            // load K,V tiles [64 x 128]: 2048 float4 each, 16 per thread
#pragma unroll
            for (int i = 0; i < 16; i++) {
                int idx = t + i * 128;
                int rr = idx >> 5, c4 = idx & 31;
                float4 kv = *reinterpret_cast<const float4*>(&g_kp[(c0 + rr) * DK + c4 * 4]);
                float* kd = &Ks[rr * KPAD + c4 * 4];
                kd[0] = kv.x; kd[1] = kv.y; kd[2] = kv.z; kd[3] = kv.w;
                float4 vv = *reinterpret_cast<const float4*>(&g_vp[(c0 + rr) * DK + c4 * 4]);
                *reinterpret_cast<float4*>(&Vs[rr * VPAD + c4 * 4]) = vv;
            }
            __syncthreads();

            // ---- S = Q @ K^T (thread tile 2 rows x 4 strided cols) ----
            float s[2][4];
#pragma unroll
            for (int i = 0; i < 2; i++)
#pragma unroll
                for (int j = 0; j < 4; j++) s[i][j] = 0.f;

            const float* qr0 = &Qs[r0l * KPAD];
            const float* qr1 = qr0 + KPAD;
            const float* kr0 = &Ks[(colg +  0) * KPAD];
            const float* kr1 = &Ks[(colg + 16) * KPAD];
            const float* kr2 = &Ks[(colg + 32) * KPAD];
            const float* kr3 = &Ks[(colg + 48) * KPAD];

#pragma unroll 4
            for (int kk = 0; kk < DK; kk++) {
                float a0 = qr0[kk], a1 = qr1[kk];
                float b0 = kr0[kk], b1 = kr1[kk], b2 = kr2[kk], b3 = kr3[kk];
                s[0][0] += a0 * b0; s[0][1] += a0 * b1; s[0][2] += a0 * b2; s[0][3] += a0 * b3;
                s[1][0] += a1 * b0; s[1][1] += a1 * b1; s[1][2] += a1 * b2; s[1][3] += a1 * b3;
            }

            // ---- online softmax per row (16 lanes of a row are in one warp) ----
#pragma unroll
            for (int i = 0; i < 2; i++) {
                const int grow = rbase + r0l + i;
                float sv[4];
                float mloc = -1e30f;
#pragma unroll
                for (int j = 0; j < 4; j++) {
                    int gcol = c0 + colg + 16 * j;
                    float x = s[i][j] * scale;
                    if (gcol > grow) x = -1e30f;
                    sv[j] = x;
                    mloc = fmaxf(mloc, x);
                }
#pragma unroll
                for (int off = 8; off > 0; off >>= 1)
                    mloc = fmaxf(mloc, __shfl_xor_sync(0xffffffffu, mloc, off));

                float m_old = m_s[r0l + i];
                float m_new = fmaxf(m_old, mloc);
                float psum = 0.f;
#pragma unroll
                for (int j = 0; j < 4; j++) {
                    float p = __expf(sv[j] - m_new);
                    Ps[(r0l + i) * PPAD + colg + 16 * j] = p;
                    psum += p;
                }
#pragma unroll
                for (int off = 8; off > 0; off >>= 1)
                    psum += __shfl_xor_sync(0xffffffffu, psum, off);

                if (colg == 0) {
                    float sc = __expf(m_old - m_new);
                    sc_s[r0l + i] = sc;
                    l_s[r0l + i]  = l_s[r0l + i] * sc + psum;
                    m_s[r0l + i]  = m_new;
                }
            }
            __syncwarp();

            // ---- rescale O, accumulate P @ V (thread tile 2 rows x 8 d) ----
            float sca = sc_s[r0l], scb = sc_s[r0l + 1];
#pragma unroll
            for (int j = 0; j < 8; j++) { o0[j] *= sca; o1[j] *= scb; }

            const float* pr0 = &Ps[r0l * PPAD];
            const float* pr1 = pr0 + PPAD;
#pragma unroll 2
            for (int c = 0; c < BN; c++) {
                float p0 = pr0[c], p1 = pr1[c];
                float4 va = *reinterpret_cast<const float4*>(&Vs[c * VPAD + dg * 8]);
                float4 vb = *reinterpret_cast<const float4*>(&Vs[c * VPAD + dg * 8 + 4]);
                o0[0] += p0 * va.x; o0[1] += p0 * va.y; o0[2] += p0 * va.z; o0[3] += p0 * va.w;
                o0[4] += p0 * vb.x; o0[5] += p0 * vb.y; o0[6] += p0 * vb.z; o0[7] += p0 * vb.w;
                o1[0] += p1 * va.x; o1[1] += p1 * va.y; o1[2] += p1 * va.z; o1[3] += p1 * va.w;
                o1[4] += p1 * vb.x; o1[5] += p1 * vb.y; o1[6] += p1 * vb.z; o1[7] += p1 * vb.w;
            }
        }

        // ---- epilogue: normalize & store ----
        {
            float inv0 = 1.f / l_s[r0l];
            float inv1 = 1.f / l_s[r0l + 1];
            int grow0 = rbase + r0l;
            int grow1 = grow0 + 1;
            float4 a, b;
            a.x = o0[0] * inv0; a.y = o0[1] * inv0; a.z = o0[2] * inv0; a.w = o0[3] * inv0;
            b.x = o0[4] * inv0; b.y = o0[5] * inv0; b.z = o0[6] * inv0; b.w = o0[7] * inv0;
            *reinterpret_cast<float4*>(&out[grow0 * DK + dg * 8])     = a;
            *reinterpret_cast<float4*>(&out[grow0 * DK + dg * 8 + 4]) = b;
            a.x = o1[0] * inv1; a.y = o1[1] * inv1; a.z = o1[2] * inv1; a.w = o1[3] * inv1;
            b.x = o1[4] * inv1; b.y = o1[5] * inv1; b.z = o1[6] * inv1; b.w = o1[7] * inv1;
            *reinterpret_cast<float4*>(&out[grow1 * DK + dg * 8])     = a;
            *reinterpret_cast<float4*>(&out[grow1 * DK + dg * 8 + 4]) = b;
        }
        __syncthreads();   // stats/smem safe before next pass
    }
}

// ---------------------------------------------------------------------------
extern "C" void kernel_launch(void* const* d_in, const int* in_sizes, int n_in,
                              void* d_out, int out_size)
{
    const float* q  = (const float*)d_in[0];
    const float* k  = (const float*)d_in[1];
    const float* v  = (const float*)d_in[2];
    const float* Wq = (const float*)d_in[3];
    const float* bq = (const float*)d_in[4];
    const float* Wk = (const float*)d_in[5];
    const float* bk = (const float*)d_in[6];
    const float* Wv = (const float*)d_in[7];
    const float* bv = (const float*)d_in[8];
    float* out = (float*)d_out;

    const int smem_bytes = (BM * KPAD + BN * KPAD + BN * VPAD + BM * PPAD + 3 * BM) * sizeof(float);
    cudaFuncSetAttribute(attn_kernel, cudaFuncAttributeMaxDynamicSharedMemorySize, smem_bytes);

    proj_kernel<<<dim3(SEQ / 32, 3), 256>>>(q, k, v, Wq, bq, Wk, bk, Wv, bv);
    attn_kernel<<<ATTN_BLOCKS, 128, smem_bytes>>>(out);
}

// round 2
// speedup vs baseline: 1.5100x; 1.5100x over previous
#include <cuda_runtime.h>
#include <math.h>

#define SEQ 4096
#define DM  1024
#define DK  128
#define BM  16
#define BN  64
#define KPAD 132
#define VPAD 132
#define PPAD 68
#define NTILES 256
#define MAXCH 4
#define TOTAL_BLOCKS 640   // sum over row tiles of ceil(16(r+1)/1024)

// Scratch (static device memory: allowed)
__device__ float g_qp[SEQ * DK];
__device__ float g_kp[SEQ * DK];
__device__ float g_vp[SEQ * DK];
__device__ float g_pO[NTILES * MAXCH * BM * DK];   // 8 MB partial O (unnormalized)
__device__ float g_pm[NTILES * MAXCH * BM];
__device__ float g_pl[NTILES * MAXCH * BM];

// ---------------------------------------------------------------------------
// Projection: OUT = X @ W + b   (X: [4096,1024], W: [1024,128])
// ---------------------------------------------------------------------------
__global__ void __launch_bounds__(256) proj_kernel(
    const float* __restrict__ q, const float* __restrict__ k, const float* __restrict__ v,
    const float* __restrict__ Wq, const float* __restrict__ bq,
    const float* __restrict__ Wk, const float* __restrict__ bk,
    const float* __restrict__ Wv, const float* __restrict__ bv)
{
    const int which = blockIdx.y;
    const float* X = (which == 0) ? q  : (which == 1) ? k  : v;
    const float* W = (which == 0) ? Wq : (which == 1) ? Wk : Wv;
    const float* B = (which == 0) ? bq : (which == 1) ? bk : bv;
    float* OUT     = (which == 0) ? g_qp : (which == 1) ? g_kp : g_vp;

    __shared__ float Xs[32 * 33];
    __shared__ float Ws[32 * 128];

    const int t    = threadIdx.x;
    const int rowg = t >> 5;
    const int colg = t & 31;
    const int r0   = blockIdx.x * 32;

    float acc[4][4];
#pragma unroll
    for (int i = 0; i < 4; i++)
#pragma unroll
        for (int j = 0; j < 4; j++) acc[i][j] = 0.f;

    for (int k0 = 0; k0 < DM; k0 += 32) {
        __syncthreads();
#pragma unroll
        for (int i = 0; i < 4; i++) {
            int idx = t + i * 256;
            int rr = idx >> 5, kk = idx & 31;
            Xs[rr * 33 + kk] = X[(r0 + rr) * DM + k0 + kk];
        }
#pragma unroll
        for (int i = 0; i < 4; i++) {
            int idx4 = t + i * 256;
            int rr = idx4 >> 5, c4 = idx4 & 31;
            float4 w = *reinterpret_cast<const float4*>(&W[(k0 + rr) * DK + c4 * 4]);
            *reinterpret_cast<float4*>(&Ws[rr * DK + c4 * 4]) = w;
        }
        __syncthreads();

#pragma unroll 4
        for (int kk = 0; kk < 32; kk++) {
            float x0 = Xs[(rowg * 4 + 0) * 33 + kk];
            float x1 = Xs[(rowg * 4 + 1) * 33 + kk];
            float x2 = Xs[(rowg * 4 + 2) * 33 + kk];
            float x3 = Xs[(rowg * 4 + 3) * 33 + kk];
            float4 w = *reinterpret_cast<const float4*>(&Ws[kk * DK + colg * 4]);
            acc[0][0] += x0 * w.x; acc[0][1] += x0 * w.y; acc[0][2] += x0 * w.z; acc[0][3] += x0 * w.w;
            acc[1][0] += x1 * w.x; acc[1][1] += x1 * w.y; acc[1][2] += x1 * w.z; acc[1][3] += x1 * w.w;
            acc[2][0] += x2 * w.x; acc[2][1] += x2 * w.y; acc[2][2] += x2 * w.z; acc[2][3] += x2 * w.w;
            acc[3][0] += x3 * w.x; acc[3][1] += x3 * w.y; acc[3][2] += x3 * w.z; acc[3][3] += x3 * w.w;
        }
    }

    float4 bias = *reinterpret_cast<const float4*>(&B[colg * 4]);
#pragma unroll
    for (int i = 0; i < 4; i++) {
        int row = r0 + rowg * 4 + i;
        float4 o;
        o.x = acc[i][0] + bias.x; o.y = acc[i][1] + bias.y;
        o.z = acc[i][2] + bias.z; o.w = acc[i][3] + bias.w;
        *reinterpret_cast<float4*>(&OUT[row * DK + colg * 4]) = o;
    }
}

// ---------------------------------------------------------------------------
// Split-KV causal flash attention partials.
// Block = (row tile r of 16 rows, kv chunk c of <=1024 cols). 128 threads.
// Writes unnormalized O + (m, l) per row to global scratch.
// ---------------------------------------------------------------------------
__global__ void __launch_bounds__(128) attn_part_kernel()
{
    extern __shared__ float sm[];
    float* Qs  = sm;                    // 16 x 132
    float* Ks  = Qs + BM * KPAD;        // 64 x 132
    float* Vs  = Ks + BN * KPAD;        // 64 x 132
    float* Ps  = Vs + BN * VPAD;        // 16 x 68
    float* m_s = Ps + BM * PPAD;        // 16
    float* l_s = m_s + BM;              // 16
    float* sc_s = l_s + BM;             // 16

    const int t    = threadIdx.x;
    const int rowg = t >> 4;            // 0..7
    const int colg = t & 15;            // 0..15
    const int r0l  = rowg * 2;
    const int dg   = colg;              // PV d-groups: d = 4*dg and 64 + 4*dg
    const float scale = 0.08838834764831845f;   // 1/sqrt(128)

    // Heavy-first block decode
    int B = TOTAL_BLOCKS - 1 - (int)blockIdx.x;
    int r, c;
    if (B < 64)       { r = B;                c = 0; }
    else if (B < 192) { int q = B - 64;  r = 64  + (q >> 1); c = q & 1; }
    else if (B < 384) { int q = B - 192; int q3 = q / 3; r = 128 + q3; c = q - q3 * 3; }
    else              { int q = B - 384; r = 192 + (q >> 2); c = q & 3; }

    const int rbase  = r * BM;
    const int c0base = c << 10;                       // c * 1024
    const int colend = min(c0base + 1024, rbase + BM);
    const int nct    = (colend - c0base + BN - 1) / BN;

    if (t < BM) { m_s[t] = -1e30f; l_s[t] = 0.f; }

    // load Q tile [16 x 128]
#pragma unroll
    for (int i = 0; i < 4; i++) {
        int idx = t + i * 128;
        int rr = idx >> 5, c4 = idx & 31;
        float4 qv = *reinterpret_cast<const float4*>(&g_qp[(rbase + rr) * DK + c4 * 4]);
        *reinterpret_cast<float4*>(&Qs[rr * KPAD + c4 * 4]) = qv;
    }

    float o0[8], o1[8];
#pragma unroll
    for (int j = 0; j < 8; j++) { o0[j] = 0.f; o1[j] = 0.f; }

    for (int tc = 0; tc < nct; tc++) {
        const int c0 = c0base + tc * BN;
        __syncthreads();

        // stage K,V tiles [64 x 128] as float4 (clamped row for OOB tail, masked later)
#pragma unroll
        for (int i = 0; i < 16; i++) {
            int idx = t + i * 128;
            int rr = idx >> 5, c4 = idx & 31;
            int gr = min(c0 + rr, SEQ - 1);
            *reinterpret_cast<float4*>(&Ks[rr * KPAD + c4 * 4]) =
                *reinterpret_cast<const float4*>(&g_kp[gr * DK + c4 * 4]);
            *reinterpret_cast<float4*>(&Vs[rr * VPAD + c4 * 4]) =
                *reinterpret_cast<const float4*>(&g_vp[gr * DK + c4 * 4]);
        }
        __syncthreads();

        // ---- S = Q @ K^T (2 rows x 4 strided cols, float4 k-steps) ----
        float s[2][4];
#pragma unroll
        for (int i = 0; i < 2; i++)
#pragma unroll
            for (int j = 0; j < 4; j++) s[i][j] = 0.f;

        const float4* qr0 = reinterpret_cast<const float4*>(&Qs[r0l * KPAD]);
        const float4* qr1 = reinterpret_cast<const float4*>(&Qs[(r0l + 1) * KPAD]);
        const float4* kr0 = reinterpret_cast<const float4*>(&Ks[(colg +  0) * KPAD]);
        const float4* kr1 = reinterpret_cast<const float4*>(&Ks[(colg + 16) * KPAD]);
        const float4* kr2 = reinterpret_cast<const float4*>(&Ks[(colg + 32) * KPAD]);
        const float4* kr3 = reinterpret_cast<const float4*>(&Ks[(colg + 48) * KPAD]);

#pragma unroll 4
        for (int k4 = 0; k4 < DK / 4; k4++) {
            float4 a0 = qr0[k4], a1 = qr1[k4];
            float4 b0 = kr0[k4], b1 = kr1[k4], b2 = kr2[k4], b3 = kr3[k4];
            s[0][0] += a0.x*b0.x; s[0][0] += a0.y*b0.y; s[0][0] += a0.z*b0.z; s[0][0] += a0.w*b0.w;
            s[0][1] += a0.x*b1.x; s[0][1] += a0.y*b1.y; s[0][1] += a0.z*b1.z; s[0][1] += a0.w*b1.w;
            s[0][2] += a0.x*b2.x; s[0][2] += a0.y*b2.y; s[0][2] += a0.z*b2.z; s[0][2] += a0.w*b2.w;
            s[0][3] += a0.x*b3.x; s[0][3] += a0.y*b3.y; s[0][3] += a0.z*b3.z; s[0][3] += a0.w*b3.w;
            s[1][0] += a1.x*b0.x; s[1][0] += a1.y*b0.y; s[1][0] += a1.z*b0.z; s[1][0] += a1.w*b0.w;
            s[1][1] += a1.x*b1.x; s[1][1] += a1.y*b1.y; s[1][1] += a1.z*b1.z; s[1][1] += a1.w*b1.w;
            s[1][2] += a1.x*b2.x; s[1][2] += a1.y*b2.y; s[1][2] += a1.z*b2.z; s[1][2] += a1.w*b2.w;
            s[1][3] += a1.x*b3.x; s[1][3] += a1.y*b3.y; s[1][3] += a1.z*b3.z; s[1][3] += a1.w*b3.w;
        }

        // ---- online softmax per row (16 lanes of a row in one half-warp) ----
#pragma unroll
        for (int i = 0; i < 2; i++) {
            const int grow = rbase + r0l + i;
            float sv[4];
            float mloc = -1e30f;
#pragma unroll
            for (int j = 0; j < 4; j++) {
                int gcol = c0 + colg + 16 * j;
                float x = s[i][j] * scale;
                if (gcol > grow) x = -1e30f;
                sv[j] = x;
                mloc = fmaxf(mloc, x);
            }
#pragma unroll
            for (int off = 8; off > 0; off >>= 1)
                mloc = fmaxf(mloc, __shfl_xor_sync(0xffffffffu, mloc, off));

            float m_old = m_s[r0l + i];
            float m_new = fmaxf(m_old, mloc);
            float psum = 0.f;
#pragma unroll
            for (int j = 0; j < 4; j++) {
                float p = __expf(sv[j] - m_new);
                Ps[(r0l + i) * PPAD + colg + 16 * j] = p;
                psum += p;
            }
#pragma unroll
            for (int off = 8; off > 0; off >>= 1)
                psum += __shfl_xor_sync(0xffffffffu, psum, off);

            if (colg == 0) {
                float sc = __expf(m_old - m_new);
                sc_s[r0l + i] = sc;
                l_s[r0l + i]  = l_s[r0l + i] * sc + psum;
                m_s[r0l + i]  = m_new;
            }
        }
        __syncwarp();

        // ---- rescale O, accumulate P @ V (2 rows, d = 4dg and 64+4dg) ----
        float sca = sc_s[r0l], scb = sc_s[r0l + 1];
#pragma unroll
        for (int j = 0; j < 8; j++) { o0[j] *= sca; o1[j] *= scb; }

        const float4* p0v = reinterpret_cast<const float4*>(&Ps[r0l * PPAD]);
        const float4* p1v = reinterpret_cast<const float4*>(&Ps[(r0l + 1) * PPAD]);
#pragma unroll 4
        for (int c4 = 0; c4 < BN / 4; c4++) {
            float4 pa = p0v[c4], pb = p1v[c4];
            float pav[4] = {pa.x, pa.y, pa.z, pa.w};
            float pbv[4] = {pb.x, pb.y, pb.z, pb.w};
#pragma unroll
            for (int j = 0; j < 4; j++) {
                int cc = c4 * 4 + j;
                float4 va = *reinterpret_cast<const float4*>(&Vs[cc * VPAD + dg * 4]);
                float4 vb = *reinterpret_cast<const float4*>(&Vs[cc * VPAD + 64 + dg * 4]);
                float p0 = pav[j], p1 = pbv[j];
                o0[0] += p0 * va.x; o0[1] += p0 * va.y; o0[2] += p0 * va.z; o0[3] += p0 * va.w;
                o0[4] += p0 * vb.x; o0[5] += p0 * vb.y; o0[6] += p0 * vb.z; o0[7] += p0 * vb.w;
                o1[0] += p1 * va.x; o1[1] += p1 * va.y; o1[2] += p1 * va.z; o1[3] += p1 * va.w;
                o1[4] += p1 * vb.x; o1[5] += p1 * vb.y; o1[6] += p1 * vb.z; o1[7] += p1 * vb.w;
            }
        }
    }

    __syncthreads();

    // ---- write unnormalized partials ----
    {
        const int pidx = r * MAXCH + c;
        float* baseO = &g_pO[pidx * BM * DK];
        float4 a;
        a.x = o0[0]; a.y = o0[1]; a.z = o0[2]; a.w = o0[3];
        *reinterpret_cast<float4*>(&baseO[r0l * DK + dg * 4]) = a;
        a.x = o0[4]; a.y = o0[5]; a.z = o0[6]; a.w = o0[7];
        *reinterpret_cast<float4*>(&baseO[r0l * DK + 64 + dg * 4]) = a;
        a.x = o1[0]; a.y = o1[1]; a.z = o1[2]; a.w = o1[3];
        *reinterpret_cast<float4*>(&baseO[(r0l + 1) * DK + dg * 4]) = a;
        a.x = o1[4]; a.y = o1[5]; a.z = o1[6]; a.w = o1[7];
        *reinterpret_cast<float4*>(&baseO[(r0l + 1) * DK + 64 + dg * 4]) = a;

        if (t < BM) {
            g_pm[pidx * BM + t] = m_s[t];
            g_pl[pidx * BM + t] = l_s[t];
        }
    }
}

// ---------------------------------------------------------------------------
// Merge partials: per row-tile, combine <=4 chunks via log-sum-exp.
// ---------------------------------------------------------------------------
__global__ void __launch_bounds__(128) merge_kernel(float* __restrict__ out)
{
    __shared__ float s_m[MAXCH * BM];
    __shared__ float s_l[MAXCH * BM];
    __shared__ float s_w[MAXCH * BM];
    __shared__ float s_inv[BM];

    const int r   = blockIdx.x;
    const int nch = (r >> 6) + 1;      // r/64 + 1
    const int t   = threadIdx.x;

    if (t < nch * BM) {
        int ch = t >> 4, row = t & 15;
        s_m[t] = g_pm[(r * MAXCH + ch) * BM + row];
        s_l[t] = g_pl[(r * MAXCH + ch) * BM + row];
    }
    __syncthreads();

    if (t < BM) {
        float mx = -1e30f;
        for (int ch = 0; ch < nch; ch++) mx = fmaxf(mx, s_m[ch * BM + t]);
        float den = 0.f;
        for (int ch = 0; ch < nch; ch++) {
            float w = __expf(s_m[ch * BM + t] - mx);
            s_w[ch * BM + t] = w;
            den += w * s_l[ch * BM + t];
        }
        s_inv[t] = 1.f / den;
    }
    __syncthreads();

    const int rbase = r * BM;
#pragma unroll
    for (int i = 0; i < 16; i++) {
        int idx = t + i * 128;
        int row = idx >> 7, d = idx & 127;
        float acc = 0.f;
        for (int ch = 0; ch < nch; ch++)
            acc += s_w[ch * BM + row] * g_pO[(r * MAXCH + ch) * BM * DK + row * DK + d];
        out[(rbase + row) * DK + d] = acc * s_inv[row];
    }
}

// ---------------------------------------------------------------------------
extern "C" void kernel_launch(void* const* d_in, const int* in_sizes, int n_in,
                              void* d_out, int out_size)
{
    const float* q  = (const float*)d_in[0];
    const float* k  = (const float*)d_in[1];
    const float* v  = (const float*)d_in[2];
    const float* Wq = (const float*)d_in[3];
    const float* bq = (const float*)d_in[4];
    const float* Wk = (const float*)d_in[5];
    const float* bk = (const float*)d_in[6];
    const float* Wv = (const float*)d_in[7];
    const float* bv = (const float*)d_in[8];
    float* out = (float*)d_out;

    const int smem_bytes = (BM * KPAD + BN * KPAD + BN * VPAD + BM * PPAD + 3 * BM) * sizeof(float);
    cudaFuncSetAttribute(attn_part_kernel, cudaFuncAttributeMaxDynamicSharedMemorySize, smem_bytes);

    proj_kernel<<<dim3(SEQ / 32, 3), 256>>>(q, k, v, Wq, bq, Wk, bk, Wv, bv);
    attn_part_kernel<<<TOTAL_BLOCKS, 128, smem_bytes>>>();
    merge_kernel<<<NTILES, 128>>>(out);
}

// round 3
// speedup vs baseline: 3.1468x; 2.0840x over previous
#include <cuda_runtime.h>
#include <math.h>
#include <stdint.h>

#define SEQ 4096
#define DM  1024
#define DK  128

// ---- attention tiling ----
#define BMA   64          // query rows per block (4 warps x 16)
#define BNA   32          // keys per inner iter
#define CHUNK 512         // keys per split-KV block
#define NTA   (SEQ / BMA) // 64 row tiles
#define MAXCH 8           // max chunks per tile
#define ABLOCKS 288       // sum_{tier=1..8} 8*tier
#define KP 132            // smem stride for 128-wide fp32 tiles
#define PP 36             // smem stride for P (16x32 per warp)

// ---- scratch (static device memory: allowed) ----
__device__ float g_qp[SEQ * DK];
__device__ float g_kp[SEQ * DK];
__device__ float g_vp[SEQ * DK];
__device__ float g_pO[NTA * MAXCH * BMA * DK];   // 16 MB partials
__device__ float g_pm[NTA * MAXCH * BMA];
__device__ float g_pl[NTA * MAXCH * BMA];

// ---------------------------------------------------------------------------
// tf32 helpers
// ---------------------------------------------------------------------------
__device__ __forceinline__ float f2tf(float f) {
    uint32_t u;
    asm("cvt.rn.tf32.f32 %0, %1;" : "=r"(u) : "f"(f));
    return __uint_as_float(u);
}

__device__ __forceinline__ void mma8(float& d0, float& d1, float& d2, float& d3,
                                     uint32_t a0, uint32_t a1, uint32_t a2, uint32_t a3,
                                     uint32_t b0, uint32_t b1)
{
    asm volatile(
        "mma.sync.aligned.m16n8k8.row.col.f32.tf32.tf32.f32 "
        "{%0,%1,%2,%3}, {%4,%5,%6,%7}, {%8,%9}, {%0,%1,%2,%3};\n"
        : "+f"(d0), "+f"(d1), "+f"(d2), "+f"(d3)
        : "r"(a0), "r"(a1), "r"(a2), "r"(a3), "r"(b0), "r"(b1));
}

__device__ __forceinline__ uint32_t ldu(const float* p) { return __float_as_uint(*p); }

// ---------------------------------------------------------------------------
// Projection via tf32 MMA: OUT = X @ W + b.  Block: 128 thr, tile 64 x 128.
// grid = (64, 3).
// ---------------------------------------------------------------------------
__global__ void __launch_bounds__(128) proj_kernel(
    const float* __restrict__ q, const float* __restrict__ k, const float* __restrict__ v,
    const float* __restrict__ Wq, const float* __restrict__ bq,
    const float* __restrict__ Wk, const float* __restrict__ bk,
    const float* __restrict__ Wv, const float* __restrict__ bv)
{
    const int which = blockIdx.y;
    const float* X = (which == 0) ? q  : (which == 1) ? k  : v;
    const float* W = (which == 0) ? Wq : (which == 1) ? Wk : Wv;
    const float* B = (which == 0) ? bq : (which == 1) ? bk : bv;
    float* OUT     = (which == 0) ? g_qp : (which == 1) ? g_kp : g_vp;

    __shared__ float Xs[64 * 36];    // 9216 B
    __shared__ float Ws[32 * KP];    // 16896 B

    const int t    = threadIdx.x;
    const int warp = t >> 5;
    const int lane = t & 31;
    const int g    = lane >> 2;      // group id 0..7
    const int tig  = lane & 3;       // thread in group
    const int r0   = blockIdx.x * 64;

    float acc[16][4];
#pragma unroll
    for (int nt = 0; nt < 16; nt++)
#pragma unroll
        for (int j = 0; j < 4; j++) acc[nt][j] = 0.f;

    for (int k0 = 0; k0 < DM; k0 += 32) {
        __syncthreads();
        // stage X chunk 64x32 (tf32-rounded)
#pragma unroll
        for (int i = 0; i < 4; i++) {
            int idx = t + i * 128;             // float4 index < 512
            int rr = idx >> 3, c4 = idx & 7;
            float4 xv = *reinterpret_cast<const float4*>(&X[(r0 + rr) * DM + k0 + c4 * 4]);
            float* d = &Xs[rr * 36 + c4 * 4];
            d[0] = f2tf(xv.x); d[1] = f2tf(xv.y); d[2] = f2tf(xv.z); d[3] = f2tf(xv.w);
        }
        // stage W chunk 32x128
#pragma unroll
        for (int i = 0; i < 8; i++) {
            int idx = t + i * 128;             // float4 index < 1024
            int rr = idx >> 5, c4 = idx & 31;
            float4 wv = *reinterpret_cast<const float4*>(&W[(k0 + rr) * DK + c4 * 4]);
            float* d = &Ws[rr * KP + c4 * 4];
            d[0] = f2tf(wv.x); d[1] = f2tf(wv.y); d[2] = f2tf(wv.z); d[3] = f2tf(wv.w);
        }
        __syncthreads();

#pragma unroll
        for (int ks = 0; ks < 4; ks++) {
            const int kk = ks * 8;
            const float* ab = &Xs[(warp * 16 + g) * 36 + kk + tig];
            uint32_t a0 = ldu(ab);
            uint32_t a1 = ldu(ab + 8 * 36);
            uint32_t a2 = ldu(ab + 4);
            uint32_t a3 = ldu(ab + 8 * 36 + 4);
#pragma unroll
            for (int nt = 0; nt < 16; nt++) {
                uint32_t b0 = ldu(&Ws[(kk + tig) * KP + nt * 8 + g]);
                uint32_t b1 = ldu(&Ws[(kk + tig + 4) * KP + nt * 8 + g]);
                mma8(acc[nt][0], acc[nt][1], acc[nt][2], acc[nt][3], a0, a1, a2, a3, b0, b1);
            }
        }
    }

    const int row0 = r0 + warp * 16 + g;
    const int row1 = row0 + 8;
#pragma unroll
    for (int nt = 0; nt < 16; nt++) {
        int col = nt * 8 + 2 * tig;
        float2 bb = *reinterpret_cast<const float2*>(&B[col]);
        float2 o0, o1;
        o0.x = acc[nt][0] + bb.x; o0.y = acc[nt][1] + bb.y;
        o1.x = acc[nt][2] + bb.x; o1.y = acc[nt][3] + bb.y;
        *reinterpret_cast<float2*>(&OUT[row0 * DK + col]) = o0;
        *reinterpret_cast<float2*>(&OUT[row1 * DK + col]) = o1;
    }
}

// ---------------------------------------------------------------------------
// Split-KV causal flash attention partials via tf32 MMA.
// Block: 128 thr (4 warps x 16 rows = 64 rows), keys in chunks of 512,
// inner tiles of 32 keys. Writes unnormalized O + (m,l) partials.
// ---------------------------------------------------------------------------
__global__ void __launch_bounds__(128) attn_part_kernel()
{
    extern __shared__ float sm[];
    float* Qs = sm;                 // 64 x 132
    float* Ks = Qs + 64 * KP;       // 32 x 132
    float* Vs = Ks + 32 * KP;       // 32 x 132
    float* Ps = Vs + 32 * KP;       // 4 warps x 16 x 36

    const int t    = threadIdx.x;
    const int warp = t >> 5;
    const int lane = t & 31;
    const int g    = lane >> 2;
    const int tig  = lane & 3;
    float* Pw = Ps + warp * (16 * PP);

    // ---- heavy-first block decode: tile r has (r/8)+1 chunks ----
    int Bd = ABLOCKS - 1 - (int)blockIdx.x;
    int tier = 1, rem = Bd;
    while (rem >= 8 * tier) { rem -= 8 * tier; tier++; }
    const int r = (tier - 1) * 8 + rem / tier;
    const int c = rem % tier;

    const int rbase  = r * BMA;
    const int c0base = c * CHUNK;
    const int colend = min(c0base + CHUNK, rbase + BMA);
    const int nct    = (colend - c0base) / BNA;   // always exact multiple

    // ---- stage Q (scale folded in, tf32-rounded) ----
    const float qscale = 0.08838834764831845f;    // 1/sqrt(128)
#pragma unroll
    for (int i = 0; i < 16; i++) {
        int idx = t + i * 128;
        int row = idx >> 5, c4 = idx & 31;
        float4 qv = *reinterpret_cast<const float4*>(&g_qp[(rbase + row) * DK + c4 * 4]);
        float* d = &Qs[row * KP + c4 * 4];
        d[0] = f2tf(qv.x * qscale); d[1] = f2tf(qv.y * qscale);
        d[2] = f2tf(qv.z * qscale); d[3] = f2tf(qv.w * qscale);
    }

    float o[16][4];
#pragma unroll
    for (int nt = 0; nt < 16; nt++)
#pragma unroll
        for (int j = 0; j < 4; j++) o[nt][j] = 0.f;

    float m0 = -1e30f, m1 = -1e30f, l0 = 0.f, l1 = 0.f;
    const int grow0 = rbase + warp * 16 + g;
    const int grow1 = grow0 + 8;

    for (int tc = 0; tc < nct; tc++) {
        const int c0 = c0base + tc * BNA;
        __syncthreads();
        // stage K,V tile 32x128 (tf32-rounded)
#pragma unroll
        for (int i = 0; i < 8; i++) {
            int idx = t + i * 128;
            int row = idx >> 5, c4 = idx & 31;
            int gr = min(c0 + row, SEQ - 1);
            float4 kv = *reinterpret_cast<const float4*>(&g_kp[gr * DK + c4 * 4]);
            float* kd = &Ks[row * KP + c4 * 4];
            kd[0] = f2tf(kv.x); kd[1] = f2tf(kv.y); kd[2] = f2tf(kv.z); kd[3] = f2tf(kv.w);
            float4 vv = *reinterpret_cast<const float4*>(&g_vp[gr * DK + c4 * 4]);
            float* vd = &Vs[row * KP + c4 * 4];
            vd[0] = f2tf(vv.x); vd[1] = f2tf(vv.y); vd[2] = f2tf(vv.z); vd[3] = f2tf(vv.w);
        }
        __syncthreads();

        // ---- S = Q K^T : warp tile 16 x 32 ----
        float s[4][4];
#pragma unroll
        for (int nt = 0; nt < 4; nt++)
#pragma unroll
            for (int j = 0; j < 4; j++) s[nt][j] = 0.f;

#pragma unroll
        for (int ks = 0; ks < 16; ks++) {
            const int kk = ks * 8;
            const float* ab = &Qs[(warp * 16 + g) * KP + kk + tig];
            uint32_t a0 = ldu(ab);
            uint32_t a1 = ldu(ab + 8 * KP);
            uint32_t a2 = ldu(ab + 4);
            uint32_t a3 = ldu(ab + 8 * KP + 4);
#pragma unroll
            for (int nt = 0; nt < 4; nt++) {
                uint32_t b0 = ldu(&Ks[(nt * 8 + g) * KP + kk + tig]);
                uint32_t b1 = ldu(&Ks[(nt * 8 + g) * KP + kk + tig + 4]);
                mma8(s[nt][0], s[nt][1], s[nt][2], s[nt][3], a0, a1, a2, a3, b0, b1);
            }
        }

        // ---- causal mask + online softmax ----
        float mloc0 = -1e30f, mloc1 = -1e30f;
#pragma unroll
        for (int nt = 0; nt < 4; nt++) {
            int colb = c0 + nt * 8 + 2 * tig;
            float x0 = (colb     <= grow0) ? s[nt][0] : -1e30f;
            float x1 = (colb + 1 <= grow0) ? s[nt][1] : -1e30f;
            float x2 = (colb     <= grow1) ? s[nt][2] : -1e30f;
            float x3 = (colb + 1 <= grow1) ? s[nt][3] : -1e30f;
            s[nt][0] = x0; s[nt][1] = x1; s[nt][2] = x2; s[nt][3] = x3;
            mloc0 = fmaxf(mloc0, fmaxf(x0, x1));
            mloc1 = fmaxf(mloc1, fmaxf(x2, x3));
        }
        mloc0 = fmaxf(mloc0, __shfl_xor_sync(0xffffffffu, mloc0, 1));
        mloc0 = fmaxf(mloc0, __shfl_xor_sync(0xffffffffu, mloc0, 2));
        mloc1 = fmaxf(mloc1, __shfl_xor_sync(0xffffffffu, mloc1, 1));
        mloc1 = fmaxf(mloc1, __shfl_xor_sync(0xffffffffu, mloc1, 2));

        float mn0 = fmaxf(m0, mloc0);
        float mn1 = fmaxf(m1, mloc1);
        float sc0 = __expf(m0 - mn0);
        float sc1 = __expf(m1 - mn1);

        float ps0 = 0.f, ps1 = 0.f;
#pragma unroll
        for (int nt = 0; nt < 4; nt++) {
            float p0 = __expf(s[nt][0] - mn0);
            float p1 = __expf(s[nt][1] - mn0);
            float p2 = __expf(s[nt][2] - mn1);
            float p3 = __expf(s[nt][3] - mn1);
            ps0 += p0 + p1;
            ps1 += p2 + p3;
            float* d0 = &Pw[g * PP + nt * 8 + 2 * tig];
            d0[0] = f2tf(p0); d0[1] = f2tf(p1);
            float* d1 = &Pw[(g + 8) * PP + nt * 8 + 2 * tig];
            d1[0] = f2tf(p2); d1[1] = f2tf(p3);
        }
        ps0 += __shfl_xor_sync(0xffffffffu, ps0, 1);
        ps0 += __shfl_xor_sync(0xffffffffu, ps0, 2);
        ps1 += __shfl_xor_sync(0xffffffffu, ps1, 1);
        ps1 += __shfl_xor_sync(0xffffffffu, ps1, 2);

        l0 = l0 * sc0 + ps0;  m0 = mn0;
        l1 = l1 * sc1 + ps1;  m1 = mn1;

        __syncwarp();

        // ---- rescale O, then O += P @ V ----
#pragma unroll
        for (int nt = 0; nt < 16; nt++) {
            o[nt][0] *= sc0; o[nt][1] *= sc0;
            o[nt][2] *= sc1; o[nt][3] *= sc1;
        }

#pragma unroll
        for (int ks = 0; ks < 4; ks++) {
            const int kk = ks * 8;
            const float* ab = &Pw[g * PP + kk + tig];
            uint32_t a0 = ldu(ab);
            uint32_t a1 = ldu(ab + 8 * PP);
            uint32_t a2 = ldu(ab + 4);
            uint32_t a3 = ldu(ab + 8 * PP + 4);
#pragma unroll
            for (int nt = 0; nt < 16; nt++) {
                uint32_t b0 = ldu(&Vs[(kk + tig) * KP + nt * 8 + g]);
                uint32_t b1 = ldu(&Vs[(kk + tig + 4) * KP + nt * 8 + g]);
                mma8(o[nt][0], o[nt][1], o[nt][2], o[nt][3], a0, a1, a2, a3, b0, b1);
            }
        }
    }

    // ---- write unnormalized partials ----
    const int pidx = r * MAXCH + c;
    float* baseO = &g_pO[(size_t)pidx * BMA * DK];
    const int row0 = warp * 16 + g;
    const int row1 = row0 + 8;
#pragma unroll
    for (int nt = 0; nt < 16; nt++) {
        int col = nt * 8 + 2 * tig;
        float2 w0; w0.x = o[nt][0]; w0.y = o[nt][1];
        float2 w1; w1.x = o[nt][2]; w1.y = o[nt][3];
        *reinterpret_cast<float2*>(&baseO[row0 * DK + col]) = w0;
        *reinterpret_cast<float2*>(&baseO[row1 * DK + col]) = w1;
    }
    if (tig == 0) {
        g_pm[pidx * BMA + row0] = m0;
        g_pm[pidx * BMA + row1] = m1;
        g_pl[pidx * BMA + row0] = l0;
        g_pl[pidx * BMA + row1] = l1;
    }
}

// ---------------------------------------------------------------------------
// Merge partials per row tile (<=8 chunks) via log-sum-exp.
// ---------------------------------------------------------------------------
__global__ void __launch_bounds__(256) merge_kernel(float* __restrict__ out)
{
    __shared__ float s_w[MAXCH * BMA];
    __shared__ float s_inv[BMA];

    const int r   = blockIdx.x;        // 0..63
    const int nch = (r >> 3) + 1;
    const int t   = threadIdx.x;

    if (t < BMA) {
        float mv[MAXCH], lv[MAXCH];
        float mx = -1e30f;
        for (int ch = 0; ch < nch; ch++) {
            mv[ch] = g_pm[(r * MAXCH + ch) * BMA + t];
            lv[ch] = g_pl[(r * MAXCH + ch) * BMA + t];
            mx = fmaxf(mx, mv[ch]);
        }
        float den = 0.f;
        for (int ch = 0; ch < nch; ch++) {
            float w = __expf(mv[ch] - mx);
            s_w[ch * BMA + t] = w;
            den += w * lv[ch];
        }
        s_inv[t] = 1.f / den;
    }
    __syncthreads();

    const int rbase = r * BMA;
#pragma unroll
    for (int i = 0; i < 32; i++) {
        int idx = t + i * 256;          // < 8192
        int row = idx >> 7, d = idx & 127;
        float acc = 0.f;
        for (int ch = 0; ch < nch; ch++)
            acc += s_w[ch * BMA + row] *
                   g_pO[((size_t)(r * MAXCH + ch) * BMA + row) * DK + d];
        out[(rbase + row) * DK + d] = acc * s_inv[row];
    }
}

// ---------------------------------------------------------------------------
extern "C" void kernel_launch(void* const* d_in, const int* in_sizes, int n_in,
                              void* d_out, int out_size)
{
    const float* q  = (const float*)d_in[0];
    const float* k  = (const float*)d_in[1];
    const float* v  = (const float*)d_in[2];
    const float* Wq = (const float*)d_in[3];
    const float* bq = (const float*)d_in[4];
    const float* Wk = (const float*)d_in[5];
    const float* bk = (const float*)d_in[6];
    const float* Wv = (const float*)d_in[7];
    const float* bv = (const float*)d_in[8];
    float* out = (float*)d_out;

    const int smem_attn = (64 * KP + 32 * KP + 32 * KP + 4 * 16 * PP) * sizeof(float); // 76800
    cudaFuncSetAttribute(attn_part_kernel, cudaFuncAttributeMaxDynamicSharedMemorySize, smem_attn);

    proj_kernel<<<dim3(SEQ / 64, 3), 128>>>(q, k, v, Wq, bq, Wk, bk, Wv, bv);
    attn_part_kernel<<<ABLOCKS, 128, smem_attn>>>();
    merge_kernel<<<NTA, 256>>>(out);
}

// round 4
// speedup vs baseline: 4.8266x; 1.5338x over previous
#include <cuda_runtime.h>
#include <math.h>
#include <stdint.h>

#define SEQ 4096
#define DM  1024
#define DK  128

// ---- proj tiling ----
#define PM  128           // rows per block
#define PKC 64            // k-chunk
#define XP  68            // Xs stride (mod 32 = 4: A-frag conflict-free)
#define WP  136           // Ws stride (mod 32 = 8: B-frag conflict-free)

// ---- attention tiling ----
#define BMA   64
#define BNA   32
#define CHUNK 512
#define NTA   (SEQ / BMA)
#define MAXCH 8
#define ABLOCKS 288       // sum_{tier=1..8} 8*tier
#define KP 132            // Q/K stride (mod 32 = 4)
#define VP 136            // V stride (mod 32 = 8: PV B-frag conflict-free)
#define PP 36

// ---- scratch ----
__device__ float g_qp[SEQ * DK];
__device__ float g_kp[SEQ * DK];
__device__ float g_vp[SEQ * DK];
__device__ float g_pO[NTA * MAXCH * BMA * DK];
__device__ float g_pm[NTA * MAXCH * BMA];
__device__ float g_pl[NTA * MAXCH * BMA];

__device__ __forceinline__ float f2tf(float f) {
    uint32_t u;
    asm("cvt.rn.tf32.f32 %0, %1;" : "=r"(u) : "f"(f));
    return __uint_as_float(u);
}

__device__ __forceinline__ void mma8(float& d0, float& d1, float& d2, float& d3,
                                     uint32_t a0, uint32_t a1, uint32_t a2, uint32_t a3,
                                     uint32_t b0, uint32_t b1)
{
    asm volatile(
        "mma.sync.aligned.m16n8k8.row.col.f32.tf32.tf32.f32 "
        "{%0,%1,%2,%3}, {%4,%5,%6,%7}, {%8,%9}, {%0,%1,%2,%3};\n"
        : "+f"(d0), "+f"(d1), "+f"(d2), "+f"(d3)
        : "r"(a0), "r"(a1), "r"(a2), "r"(a3), "r"(b0), "r"(b1));
}

__device__ __forceinline__ uint32_t ldu(const float* p) { return __float_as_uint(*p); }

// ---------------------------------------------------------------------------
// Projection: OUT = (X @ W + b) * osc.  256 thr, tile 128x128, reg-pipelined.
// grid = (32, 3). osc folds 1/sqrt(DK) into the Q projection.
// ---------------------------------------------------------------------------
__global__ void __launch_bounds__(256) proj_kernel(
    const float* __restrict__ q, const float* __restrict__ k, const float* __restrict__ v,
    const float* __restrict__ Wq, const float* __restrict__ bq,
    const float* __restrict__ Wk, const float* __restrict__ bk,
    const float* __restrict__ Wv, const float* __restrict__ bv)
{
    extern __shared__ float psm[];
    float* Xs = psm;              // 128 x 68
    float* Ws = Xs + PM * XP;     // 64 x 136

    const int which = blockIdx.y;
    const float* X = (which == 0) ? q  : (which == 1) ? k  : v;
    const float* W = (which == 0) ? Wq : (which == 1) ? Wk : Wv;
    const float* B = (which == 0) ? bq : (which == 1) ? bk : bv;
    float* OUT     = (which == 0) ? g_qp : (which == 1) ? g_kp : g_vp;
    const float osc = (which == 0) ? 0.08838834764831845f : 1.0f;

    const int t    = threadIdx.x;
    const int warp = t >> 5;          // 0..7 -> rows warp*16
    const int lane = t & 31;
    const int g    = lane >> 2;
    const int tig  = lane & 3;
    const int r0   = blockIdx.x * PM;

    float4 xr[8], wr[8];
    // prologue loads (chunk 0)
#pragma unroll
    for (int i = 0; i < 8; i++) {
        int idx = t + i * 256;               // X: 128 rows x 16 float4
        int row = idx >> 4, c4 = idx & 15;
        xr[i] = *reinterpret_cast<const float4*>(&X[(r0 + row) * DM + c4 * 4]);
    }
#pragma unroll
    for (int i = 0; i < 8; i++) {
        int idx = t + i * 256;               // W: 64 rows x 32 float4
        int row = idx >> 5, c4 = idx & 31;
        wr[i] = *reinterpret_cast<const float4*>(&W[row * DK + c4 * 4]);
    }

    float acc[16][4];
#pragma unroll
    for (int nt = 0; nt < 16; nt++)
#pragma unroll
        for (int j = 0; j < 4; j++) acc[nt][j] = 0.f;

    for (int kc = 0; kc < DM / PKC; kc++) {
        // store staged regs -> smem (tf32-rounded)
#pragma unroll
        for (int i = 0; i < 8; i++) {
            int idx = t + i * 256;
            int row = idx >> 4, c4 = idx & 15;
            float* d = &Xs[row * XP + c4 * 4];
            d[0] = f2tf(xr[i].x); d[1] = f2tf(xr[i].y); d[2] = f2tf(xr[i].z); d[3] = f2tf(xr[i].w);
        }
#pragma unroll
        for (int i = 0; i < 8; i++) {
            int idx = t + i * 256;
            int row = idx >> 5, c4 = idx & 31;
            float* d = &Ws[row * WP + c4 * 4];
            d[0] = f2tf(wr[i].x); d[1] = f2tf(wr[i].y); d[2] = f2tf(wr[i].z); d[3] = f2tf(wr[i].w);
        }
        __syncthreads();

        // prefetch next chunk (LDGs overlap the MMA below)
        if (kc + 1 < DM / PKC) {
            const int k0 = (kc + 1) * PKC;
#pragma unroll
            for (int i = 0; i < 8; i++) {
                int idx = t + i * 256;
                int row = idx >> 4, c4 = idx & 15;
                xr[i] = *reinterpret_cast<const float4*>(&X[(r0 + row) * DM + k0 + c4 * 4]);
            }
#pragma unroll
            for (int i = 0; i < 8; i++) {
                int idx = t + i * 256;
                int row = idx >> 5, c4 = idx & 31;
                wr[i] = *reinterpret_cast<const float4*>(&W[(k0 + row) * DK + c4 * 4]);
            }
        }

#pragma unroll
        for (int ks = 0; ks < 8; ks++) {
            const int kk = ks * 8;
            const float* ab = &Xs[(warp * 16 + g) * XP + kk + tig];
            uint32_t a0 = ldu(ab);
            uint32_t a1 = ldu(ab + 8 * XP);
            uint32_t a2 = ldu(ab + 4);
            uint32_t a3 = ldu(ab + 8 * XP + 4);
#pragma unroll
            for (int nt = 0; nt < 16; nt++) {
                uint32_t b0 = ldu(&Ws[(kk + tig) * WP + nt * 8 + g]);
                uint32_t b1 = ldu(&Ws[(kk + tig + 4) * WP + nt * 8 + g]);
                mma8(acc[nt][0], acc[nt][1], acc[nt][2], acc[nt][3], a0, a1, a2, a3, b0, b1);
            }
        }
        __syncthreads();
    }

    const int row0 = r0 + warp * 16 + g;
    const int row1 = row0 + 8;
#pragma unroll
    for (int nt = 0; nt < 16; nt++) {
        int col = nt * 8 + 2 * tig;
        float2 bb = *reinterpret_cast<const float2*>(&B[col]);
        float2 o0, o1;
        o0.x = (acc[nt][0] + bb.x) * osc; o0.y = (acc[nt][1] + bb.y) * osc;
        o1.x = (acc[nt][2] + bb.x) * osc; o1.y = (acc[nt][3] + bb.y) * osc;
        *reinterpret_cast<float2*>(&OUT[row0 * DK + col]) = o0;
        *reinterpret_cast<float2*>(&OUT[row1 * DK + col]) = o1;
    }
}

// ---------------------------------------------------------------------------
// Split-KV causal flash attention partials (tf32 MMA, reg-pipelined K/V).
// 128 thr = 4 warps x 16 rows. Q comes pre-scaled by 1/sqrt(DK).
// ---------------------------------------------------------------------------
__global__ void __launch_bounds__(128) attn_part_kernel()
{
    extern __shared__ float sm[];
    float* Qs = sm;                 // 64 x 132
    float* Ks = Qs + 64 * KP;       // 32 x 132
    float* Vs = Ks + 32 * KP;       // 32 x 136
    float* Ps = Vs + 32 * VP;       // 4 x 16 x 36

    const int t    = threadIdx.x;
    const int warp = t >> 5;
    const int lane = t & 31;
    const int g    = lane >> 2;
    const int tig  = lane & 3;
    float* Pw = Ps + warp * (16 * PP);

    // heavy-first decode: tile r has (r/8)+1 chunks
    int Bd = ABLOCKS - 1 - (int)blockIdx.x;
    int tier = 1, rem = Bd;
    while (rem >= 8 * tier) { rem -= 8 * tier; tier++; }
    const int r = (tier - 1) * 8 + rem / tier;
    const int c = rem % tier;

    const int rbase  = r * BMA;
    const int c0base = c * CHUNK;
    const int colend = min(c0base + CHUNK, rbase + BMA);
    const int nct    = (colend - c0base) / BNA;

    // stage Q (already scaled in proj)
#pragma unroll
    for (int i = 0; i < 16; i++) {
        int idx = t + i * 128;
        int row = idx >> 5, c4 = idx & 31;
        float4 qv = *reinterpret_cast<const float4*>(&g_qp[(rbase + row) * DK + c4 * 4]);
        float* d = &Qs[row * KP + c4 * 4];
        d[0] = f2tf(qv.x); d[1] = f2tf(qv.y); d[2] = f2tf(qv.z); d[3] = f2tf(qv.w);
    }

    // prologue K/V loads (tile 0)
    float4 kr[8], vr[8];
#pragma unroll
    for (int i = 0; i < 8; i++) {
        int idx = t + i * 128;
        int row = idx >> 5, c4 = idx & 31;
        int gr = min(c0base + row, SEQ - 1);
        kr[i] = *reinterpret_cast<const float4*>(&g_kp[gr * DK + c4 * 4]);
        vr[i] = *reinterpret_cast<const float4*>(&g_vp[gr * DK + c4 * 4]);
    }

    float o[16][4];
#pragma unroll
    for (int nt = 0; nt < 16; nt++)
#pragma unroll
        for (int j = 0; j < 4; j++) o[nt][j] = 0.f;

    float m0 = -1e30f, m1 = -1e30f, l0 = 0.f, l1 = 0.f;
    const int grow0 = rbase + warp * 16 + g;
    const int grow1 = grow0 + 8;

    for (int tc = 0; tc < nct; tc++) {
        const int c0 = c0base + tc * BNA;

        // store staged K/V -> smem
#pragma unroll
        for (int i = 0; i < 8; i++) {
            int idx = t + i * 128;
            int row = idx >> 5, c4 = idx & 31;
            float* kd = &Ks[row * KP + c4 * 4];
            kd[0] = f2tf(kr[i].x); kd[1] = f2tf(kr[i].y); kd[2] = f2tf(kr[i].z); kd[3] = f2tf(kr[i].w);
            float* vd = &Vs[row * VP + c4 * 4];
            vd[0] = f2tf(vr[i].x); vd[1] = f2tf(vr[i].y); vd[2] = f2tf(vr[i].z); vd[3] = f2tf(vr[i].w);
        }
        __syncthreads();

        // prefetch next K/V tile (overlaps MMAs below)
        if (tc + 1 < nct) {
            const int c0n = c0 + BNA;
#pragma unroll
            for (int i = 0; i < 8; i++) {
                int idx = t + i * 128;
                int row = idx >> 5, c4 = idx & 31;
                int gr = min(c0n + row, SEQ - 1);
                kr[i] = *reinterpret_cast<const float4*>(&g_kp[gr * DK + c4 * 4]);
                vr[i] = *reinterpret_cast<const float4*>(&g_vp[gr * DK + c4 * 4]);
            }
        }

        // ---- S = Q K^T : warp tile 16 x 32 ----
        float s[4][4];
#pragma unroll
        for (int nt = 0; nt < 4; nt++)
#pragma unroll
            for (int j = 0; j < 4; j++) s[nt][j] = 0.f;

#pragma unroll
        for (int ks = 0; ks < 16; ks++) {
            const int kk = ks * 8;
            const float* ab = &Qs[(warp * 16 + g) * KP + kk + tig];
            uint32_t a0 = ldu(ab);
            uint32_t a1 = ldu(ab + 8 * KP);
            uint32_t a2 = ldu(ab + 4);
            uint32_t a3 = ldu(ab + 8 * KP + 4);
#pragma unroll
            for (int nt = 0; nt < 4; nt++) {
                uint32_t b0 = ldu(&Ks[(nt * 8 + g) * KP + kk + tig]);
                uint32_t b1 = ldu(&Ks[(nt * 8 + g) * KP + kk + tig + 4]);
                mma8(s[nt][0], s[nt][1], s[nt][2], s[nt][3], a0, a1, a2, a3, b0, b1);
            }
        }

        // ---- causal mask + online softmax ----
        float mloc0 = -1e30f, mloc1 = -1e30f;
#pragma unroll
        for (int nt = 0; nt < 4; nt++) {
            int colb = c0 + nt * 8 + 2 * tig;
            float x0 = (colb     <= grow0) ? s[nt][0] : -1e30f;
            float x1 = (colb + 1 <= grow0) ? s[nt][1] : -1e30f;
            float x2 = (colb     <= grow1) ? s[nt][2] : -1e30f;
            float x3 = (colb + 1 <= grow1) ? s[nt][3] : -1e30f;
            s[nt][0] = x0; s[nt][1] = x1; s[nt][2] = x2; s[nt][3] = x3;
            mloc0 = fmaxf(mloc0, fmaxf(x0, x1));
            mloc1 = fmaxf(mloc1, fmaxf(x2, x3));
        }
        mloc0 = fmaxf(mloc0, __shfl_xor_sync(0xffffffffu, mloc0, 1));
        mloc0 = fmaxf(mloc0, __shfl_xor_sync(0xffffffffu, mloc0, 2));
        mloc1 = fmaxf(mloc1, __shfl_xor_sync(0xffffffffu, mloc1, 1));
        mloc1 = fmaxf(mloc1, __shfl_xor_sync(0xffffffffu, mloc1, 2));

        float mn0 = fmaxf(m0, mloc0);
        float mn1 = fmaxf(m1, mloc1);
        float sc0 = __expf(m0 - mn0);
        float sc1 = __expf(m1 - mn1);

        float ps0 = 0.f, ps1 = 0.f;
#pragma unroll
        for (int nt = 0; nt < 4; nt++) {
            float p0 = __expf(s[nt][0] - mn0);
            float p1 = __expf(s[nt][1] - mn0);
            float p2 = __expf(s[nt][2] - mn1);
            float p3 = __expf(s[nt][3] - mn1);
            ps0 += p0 + p1;
            ps1 += p2 + p3;
            float* d0 = &Pw[g * PP + nt * 8 + 2 * tig];
            d0[0] = f2tf(p0); d0[1] = f2tf(p1);
            float* d1 = &Pw[(g + 8) * PP + nt * 8 + 2 * tig];
            d1[0] = f2tf(p2); d1[1] = f2tf(p3);
        }
        ps0 += __shfl_xor_sync(0xffffffffu, ps0, 1);
        ps0 += __shfl_xor_sync(0xffffffffu, ps0, 2);
        ps1 += __shfl_xor_sync(0xffffffffu, ps1, 1);
        ps1 += __shfl_xor_sync(0xffffffffu, ps1, 2);

        l0 = l0 * sc0 + ps0;  m0 = mn0;
        l1 = l1 * sc1 + ps1;  m1 = mn1;

        __syncwarp();

        // ---- rescale O, then O += P @ V ----
#pragma unroll
        for (int nt = 0; nt < 16; nt++) {
            o[nt][0] *= sc0; o[nt][1] *= sc0;
            o[nt][2] *= sc1; o[nt][3] *= sc1;
        }

#pragma unroll
        for (int ks = 0; ks < 4; ks++) {
            const int kk = ks * 8;
            const float* ab = &Pw[g * PP + kk + tig];
            uint32_t a0 = ldu(ab);
            uint32_t a1 = ldu(ab + 8 * PP);
            uint32_t a2 = ldu(ab + 4);
            uint32_t a3 = ldu(ab + 8 * PP + 4);
#pragma unroll
            for (int nt = 0; nt < 16; nt++) {
                uint32_t b0 = ldu(&Vs[(kk + tig) * VP + nt * 8 + g]);
                uint32_t b1 = ldu(&Vs[(kk + tig + 4) * VP + nt * 8 + g]);
                mma8(o[nt][0], o[nt][1], o[nt][2], o[nt][3], a0, a1, a2, a3, b0, b1);
            }
        }
        __syncthreads();   // smem free for next tile's staging stores
    }

    // ---- write unnormalized partials ----
    const int pidx = r * MAXCH + c;
    float* baseO = &g_pO[(size_t)pidx * BMA * DK];
    const int row0 = warp * 16 + g;
    const int row1 = row0 + 8;
#pragma unroll
    for (int nt = 0; nt < 16; nt++) {
        int col = nt * 8 + 2 * tig;
        float2 w0; w0.x = o[nt][0]; w0.y = o[nt][1];
        float2 w1; w1.x = o[nt][2]; w1.y = o[nt][3];
        *reinterpret_cast<float2*>(&baseO[row0 * DK + col]) = w0;
        *reinterpret_cast<float2*>(&baseO[row1 * DK + col]) = w1;
    }
    if (tig == 0) {
        g_pm[pidx * BMA + row0] = m0;
        g_pm[pidx * BMA + row1] = m1;
        g_pl[pidx * BMA + row0] = l0;
        g_pl[pidx * BMA + row1] = l1;
    }
}

// ---------------------------------------------------------------------------
// Merge partials: grid 256 blocks, block (r, quarter) handles 16 rows x 128 d.
// ---------------------------------------------------------------------------
__global__ void __launch_bounds__(256) merge_kernel(float* __restrict__ out)
{
    __shared__ float s_w[MAXCH * 16];
    __shared__ float s_inv[16];

    const int r   = blockIdx.x >> 2;
    const int qq  = blockIdx.x & 3;
    const int nch = (r >> 3) + 1;
    const int t   = threadIdx.x;

    if (t < 16) {
        int row = qq * 16 + t;
        float mv[MAXCH], lv[MAXCH];
        float mx = -1e30f;
        for (int ch = 0; ch < nch; ch++) {
            mv[ch] = g_pm[(r * MAXCH + ch) * BMA + row];
            lv[ch] = g_pl[(r * MAXCH + ch) * BMA + row];
            mx = fmaxf(mx, mv[ch]);
        }
        float den = 0.f;
        for (int ch = 0; ch < nch; ch++) {
            float w = __expf(mv[ch] - mx);
            s_w[ch * 16 + t] = w;
            den += w * lv[ch];
        }
        s_inv[t] = 1.f / den;
    }
    __syncthreads();

#pragma unroll
    for (int i = 0; i < 8; i++) {
        int idx = t + i * 256;           // 2048 = 16 rows x 128
        int row16 = idx >> 7, d = idx & 127;
        int row = qq * 16 + row16;
        float acc = 0.f;
        for (int ch = 0; ch < nch; ch++)
            acc += s_w[ch * 16 + row16] *
                   g_pO[((size_t)(r * MAXCH + ch) * BMA + row) * DK + d];
        out[(r * BMA + row) * DK + d] = acc * s_inv[row16];
    }
}

// ---------------------------------------------------------------------------
extern "C" void kernel_launch(void* const* d_in, const int* in_sizes, int n_in,
                              void* d_out, int out_size)
{
    const float* q  = (const float*)d_in[0];
    const float* k  = (const float*)d_in[1];
    const float* v  = (const float*)d_in[2];
    const float* Wq = (const float*)d_in[3];
    const float* bq = (const float*)d_in[4];
    const float* Wk = (const float*)d_in[5];
    const float* bk = (const float*)d_in[6];
    const float* Wv = (const float*)d_in[7];
    const float* bv = (const float*)d_in[8];
    float* out = (float*)d_out;

    const int smem_proj = (PM * XP + PKC * WP) * sizeof(float);                 // 69632
    const int smem_attn = (64 * KP + 32 * KP + 32 * VP + 4 * 16 * PP) * sizeof(float); // 77312
    cudaFuncSetAttribute(proj_kernel, cudaFuncAttributeMaxDynamicSharedMemorySize, smem_proj);
    cudaFuncSetAttribute(attn_part_kernel, cudaFuncAttributeMaxDynamicSharedMemorySize, smem_attn);

    proj_kernel<<<dim3(SEQ / PM, 3), 256, smem_proj>>>(q, k, v, Wq, bq, Wk, bk, Wv, bv);
    attn_part_kernel<<<ABLOCKS, 128, smem_attn>>>();
    merge_kernel<<<NTA * 4, 256>>>(out);
}

// round 5
// speedup vs baseline: 5.6851x; 1.1779x over previous
#include <cuda_runtime.h>
#include <math.h>
#include <stdint.h>

#define SEQ 4096
#define DM  1024
#define DK  128

// ---- proj tiling ----
#define PM   64           // rows per block
#define PKC  32           // k-chunk
#define PNCH (DM / PKC)   // 32 chunks
#define XP   36           // Xs stride (mod 32 = 4)
#define WP   136          // Ws stride (mod 32 = 8)

// ---- attention tiling ----
#define BMA   64
#define BNA   32
#define CHUNK 512
#define NTA   (SEQ / BMA)
#define MAXCH 8
#define ABLOCKS 288       // sum_{tier=1..8} 8*tier
#define KP 132            // Q/K stride (mod 32 = 4)
#define VP 136            // V stride (mod 32 = 8)
#define PP 36

// ---- scratch ----
__device__ float g_qp[SEQ * DK];
__device__ float g_kp[SEQ * DK];
__device__ float g_vp[SEQ * DK];
__device__ float g_wt[3 * DM * DK];              // tf32-rounded weights
__device__ float g_pO[NTA * MAXCH * BMA * DK];
__device__ float g_pm[NTA * MAXCH * BMA];
__device__ float g_pl[NTA * MAXCH * BMA];

__device__ __forceinline__ float f2tf(float f) {
    uint32_t u;
    asm("cvt.rn.tf32.f32 %0, %1;" : "=r"(u) : "f"(f));
    return __uint_as_float(u);
}

__device__ __forceinline__ void mma8(float& d0, float& d1, float& d2, float& d3,
                                     uint32_t a0, uint32_t a1, uint32_t a2, uint32_t a3,
                                     uint32_t b0, uint32_t b1)
{
    asm volatile(
        "mma.sync.aligned.m16n8k8.row.col.f32.tf32.tf32.f32 "
        "{%0,%1,%2,%3}, {%4,%5,%6,%7}, {%8,%9}, {%0,%1,%2,%3};\n"
        : "+f"(d0), "+f"(d1), "+f"(d2), "+f"(d3)
        : "r"(a0), "r"(a1), "r"(a2), "r"(a3), "r"(b0), "r"(b1));
}

__device__ __forceinline__ uint32_t ldu(const float* p) { return __float_as_uint(*p); }
// integer round-to-nearest (half-up) to tf32; consumer MMA truncates low 13 bits
__device__ __forceinline__ uint32_t ldu_rn(const float* p) { return __float_as_uint(*p) + 0x1000u; }

__device__ __forceinline__ void cp16(void* dst_smem, const void* src_gmem) {
    uint32_t d = (uint32_t)__cvta_generic_to_shared(dst_smem);
    asm volatile("cp.async.cg.shared.global [%0], [%1], 16;" :: "r"(d), "l"(src_gmem));
}
#define CP_COMMIT() asm volatile("cp.async.commit_group;")
#define CP_WAIT(n)  asm volatile("cp.async.wait_group %0;" :: "n"(n))

// ---------------------------------------------------------------------------
// Prep: round W matrices to tf32 once. grid (128, 3), 256 thr.
// ---------------------------------------------------------------------------
__global__ void __launch_bounds__(256) prep_kernel(
    const float* __restrict__ Wq, const float* __restrict__ Wk, const float* __restrict__ Wv)
{
    const int which = blockIdx.y;
    const float* W = (which == 0) ? Wq : (which == 1) ? Wk : Wv;
    float* D = g_wt + which * DM * DK;
    int i4 = blockIdx.x * 256 + threadIdx.x;     // float4 index < 32768
    float4 w = *reinterpret_cast<const float4*>(&W[i4 * 4]);
    float4 o;
    o.x = f2tf(w.x); o.y = f2tf(w.y); o.z = f2tf(w.z); o.w = f2tf(w.w);
    *reinterpret_cast<float4*>(&D[i4 * 4]) = o;
}

// ---------------------------------------------------------------------------
// Projection: OUT = round_tf32((X @ W + b) * osc).  256 thr, tile 64 x 128.
// Warp grid 2x4 (warp tile 32x64). cp.async double-buffered, k-chunk 32.
// grid = (64, 3).
// ---------------------------------------------------------------------------
__global__ void __launch_bounds__(256, 2) proj_kernel(
    const float* __restrict__ q, const float* __restrict__ k, const float* __restrict__ v,
    const float* __restrict__ bq, const float* __restrict__ bk, const float* __restrict__ bv)
{
    extern __shared__ float psm[];
    // layout: Xs0, Xs1 (64x36), Ws0, Ws1 (32x136)
    float* Xs0 = psm;
    float* Xs1 = Xs0 + PM * XP;
    float* Ws0 = Xs1 + PM * XP;
    float* Ws1 = Ws0 + PKC * WP;

    const int which = blockIdx.y;
    const float* X  = (which == 0) ? q  : (which == 1) ? k  : v;
    const float* Wt = g_wt + which * DM * DK;
    const float* B  = (which == 0) ? bq : (which == 1) ? bk : bv;
    float* OUT      = (which == 0) ? g_qp : (which == 1) ? g_kp : g_vp;
    const float osc = (which == 0) ? 0.08838834764831845f : 1.0f;

    const int t    = threadIdx.x;
    const int warp = t >> 5;
    const int lane = t & 31;
    const int wr   = warp >> 2;       // 0..1: rows wr*32
    const int wc   = warp & 3;        // 0..3: cols wc*32
    const int g    = lane >> 2;
    const int tig  = lane & 3;
    const int r0   = blockIdx.x * PM;

    // issue one k-chunk's copies into stage buffers
    auto issue = [&](int kc, float* Xs, float* Ws) {
        const int k0 = kc * PKC;
        // X: 64 rows x 32 floats = 512 x16B, 2/thread
#pragma unroll
        for (int i = 0; i < 2; i++) {
            int idx = t + i * 256;
            int row = idx >> 3, c4 = idx & 7;
            cp16(&Xs[row * XP + c4 * 4], &X[(r0 + row) * DM + k0 + c4 * 4]);
        }
        // W: 32 rows x 128 floats = 1024 x16B, 4/thread
#pragma unroll
        for (int i = 0; i < 4; i++) {
            int idx = t + i * 256;
            int row = idx >> 5, c4 = idx & 31;
            cp16(&Ws[row * WP + c4 * 4], &Wt[(k0 + row) * DK + c4 * 4]);
        }
        CP_COMMIT();
    };

    float acc[8][4];                  // [mf*4+nf][4]
#pragma unroll
    for (int i = 0; i < 8; i++)
#pragma unroll
        for (int j = 0; j < 4; j++) acc[i][j] = 0.f;

    issue(0, Xs0, Ws0);
    issue(1, Xs1, Ws1);
    CP_WAIT(1);
    __syncthreads();

    for (int kc = 0; kc < PNCH; kc++) {
        float* Xs = (kc & 1) ? Xs1 : Xs0;
        float* Ws = (kc & 1) ? Ws1 : Ws0;

#pragma unroll
        for (int ks = 0; ks < 4; ks++) {
            const int kk = ks * 8;
            // A-frags (2 m-frags), integer-rounded to tf32
            uint32_t a[2][4];
#pragma unroll
            for (int mf = 0; mf < 2; mf++) {
                const float* ab = &Xs[(wr * 32 + mf * 16 + g) * XP + kk + tig];
                a[mf][0] = ldu_rn(ab);
                a[mf][1] = ldu_rn(ab + 8 * XP);
                a[mf][2] = ldu_rn(ab + 4);
                a[mf][3] = ldu_rn(ab + 8 * XP + 4);
            }
            // B-frags (4 n-frags), pre-rounded
            uint32_t b[4][2];
#pragma unroll
            for (int nf = 0; nf < 4; nf++) {
                b[nf][0] = ldu(&Ws[(kk + tig) * WP + wc * 32 + nf * 8 + g]);
                b[nf][1] = ldu(&Ws[(kk + tig + 4) * WP + wc * 32 + nf * 8 + g]);
            }
#pragma unroll
            for (int mf = 0; mf < 2; mf++)
#pragma unroll
                for (int nf = 0; nf < 4; nf++)
                    mma8(acc[mf * 4 + nf][0], acc[mf * 4 + nf][1],
                         acc[mf * 4 + nf][2], acc[mf * 4 + nf][3],
                         a[mf][0], a[mf][1], a[mf][2], a[mf][3],
                         b[nf][0], b[nf][1]);
        }
        __syncthreads();
        if (kc + 2 < PNCH) {
            issue(kc + 2, Xs, Ws);   // reuse just-consumed buffers
            CP_WAIT(1);
            __syncthreads();
        } else if (kc + 1 < PNCH) {
            CP_WAIT(0);
            __syncthreads();
        }
    }

    // epilogue: bias, scale, tf32-round, store
#pragma unroll
    for (int mf = 0; mf < 2; mf++) {
        const int row0 = r0 + wr * 32 + mf * 16 + g;
        const int row1 = row0 + 8;
#pragma unroll
        for (int nf = 0; nf < 4; nf++) {
            int col = wc * 32 + nf * 8 + 2 * tig;
            float2 bb = *reinterpret_cast<const float2*>(&B[col]);
            float2 o0, o1;
            o0.x = f2tf((acc[mf * 4 + nf][0] + bb.x) * osc);
            o0.y = f2tf((acc[mf * 4 + nf][1] + bb.y) * osc);
            o1.x = f2tf((acc[mf * 4 + nf][2] + bb.x) * osc);
            o1.y = f2tf((acc[mf * 4 + nf][3] + bb.y) * osc);
            *reinterpret_cast<float2*>(&OUT[row0 * DK + col]) = o0;
            *reinterpret_cast<float2*>(&OUT[row1 * DK + col]) = o1;
        }
    }
}

// ---------------------------------------------------------------------------
// Split-KV causal flash attention partials. Inputs pre-rounded to tf32.
// 128 thr = 4 warps x 16 rows. cp.async double-buffered K/V, Q-frags cached
// in registers across tiles.
// ---------------------------------------------------------------------------
__global__ void __launch_bounds__(128, 2) attn_part_kernel()
{
    extern __shared__ float sm[];
    float* Qs  = sm;                    // 64 x 132
    float* Ks0 = Qs + 64 * KP;          // 32 x 132
    float* Ks1 = Ks0 + 32 * KP;
    float* Vs0 = Ks1 + 32 * KP;         // 32 x 136
    float* Vs1 = Vs0 + 32 * VP;
    float* Ps  = Vs1 + 32 * VP;         // 4 x 16 x 36

    const int t    = threadIdx.x;
    const int warp = t >> 5;
    const int lane = t & 31;
    const int g    = lane >> 2;
    const int tig  = lane & 3;
    float* Pw = Ps + warp * (16 * PP);

    // heavy-first decode: tile r has (r/8)+1 chunks
    int Bd = ABLOCKS - 1 - (int)blockIdx.x;
    int tier = 1, rem = Bd;
    while (rem >= 8 * tier) { rem -= 8 * tier; tier++; }
    const int r = (tier - 1) * 8 + rem / tier;
    const int c = rem % tier;

    const int rbase  = r * BMA;
    const int c0base = c * CHUNK;
    const int colend = min(c0base + CHUNK, rbase + BMA);
    const int nct    = (colend - c0base) / BNA;

    auto issue_kv = [&](int tc, float* Kd, float* Vd) {
        const int c0 = c0base + tc * BNA;
#pragma unroll
        for (int i = 0; i < 8; i++) {
            int idx = t + i * 128;
            int row = idx >> 5, c4 = idx & 31;
            cp16(&Kd[row * KP + c4 * 4], &g_kp[(c0 + row) * DK + c4 * 4]);
            cp16(&Vd[row * VP + c4 * 4], &g_vp[(c0 + row) * DK + c4 * 4]);
        }
        CP_COMMIT();
    };

    // group 0: Q + KV tile 0
    {
#pragma unroll
        for (int i = 0; i < 16; i++) {
            int idx = t + i * 128;
            int row = idx >> 5, c4 = idx & 31;
            cp16(&Qs[row * KP + c4 * 4], &g_qp[(rbase + row) * DK + c4 * 4]);
        }
        issue_kv(0, Ks0, Vs0);
    }
    if (nct > 1) {
        issue_kv(1, Ks1, Vs1);
        CP_WAIT(1);
    } else {
        CP_WAIT(0);
    }
    __syncthreads();

    // cache Q A-fragments in registers (fixed across tiles)
    uint32_t qf[16][4];
#pragma unroll
    for (int ks = 0; ks < 16; ks++) {
        const int kk = ks * 8;
        const float* ab = &Qs[(warp * 16 + g) * KP + kk + tig];
        qf[ks][0] = ldu(ab);
        qf[ks][1] = ldu(ab + 8 * KP);
        qf[ks][2] = ldu(ab + 4);
        qf[ks][3] = ldu(ab + 8 * KP + 4);
    }

    float o[16][4];
#pragma unroll
    for (int nt = 0; nt < 16; nt++)
#pragma unroll
        for (int j = 0; j < 4; j++) o[nt][j] = 0.f;

    float m0 = -1e30f, m1 = -1e30f, l0 = 0.f, l1 = 0.f;
    const int grow0 = rbase + warp * 16 + g;
    const int grow1 = grow0 + 8;

    for (int tc = 0; tc < nct; tc++) {
        const int c0 = c0base + tc * BNA;
        float* Ks = (tc & 1) ? Ks1 : Ks0;
        float* Vs = (tc & 1) ? Vs1 : Vs0;

        // ---- S = Q K^T : warp tile 16 x 32 ----
        float s[4][4];
#pragma unroll
        for (int nt = 0; nt < 4; nt++)
#pragma unroll
            for (int j = 0; j < 4; j++) s[nt][j] = 0.f;

#pragma unroll
        for (int ks = 0; ks < 16; ks++) {
            const int kk = ks * 8;
#pragma unroll
            for (int nt = 0; nt < 4; nt++) {
                uint32_t b0 = ldu(&Ks[(nt * 8 + g) * KP + kk + tig]);
                uint32_t b1 = ldu(&Ks[(nt * 8 + g) * KP + kk + tig + 4]);
                mma8(s[nt][0], s[nt][1], s[nt][2], s[nt][3],
                     qf[ks][0], qf[ks][1], qf[ks][2], qf[ks][3], b0, b1);
            }
        }

        // ---- causal mask + online softmax ----
        float mloc0 = -1e30f, mloc1 = -1e30f;
#pragma unroll
        for (int nt = 0; nt < 4; nt++) {
            int colb = c0 + nt * 8 + 2 * tig;
            float x0 = (colb     <= grow0) ? s[nt][0] : -1e30f;
            float x1 = (colb + 1 <= grow0) ? s[nt][1] : -1e30f;
            float x2 = (colb     <= grow1) ? s[nt][2] : -1e30f;
            float x3 = (colb + 1 <= grow1) ? s[nt][3] : -1e30f;
            s[nt][0] = x0; s[nt][1] = x1; s[nt][2] = x2; s[nt][3] = x3;
            mloc0 = fmaxf(mloc0, fmaxf(x0, x1));
            mloc1 = fmaxf(mloc1, fmaxf(x2, x3));
        }
        mloc0 = fmaxf(mloc0, __shfl_xor_sync(0xffffffffu, mloc0, 1));
        mloc0 = fmaxf(mloc0, __shfl_xor_sync(0xffffffffu, mloc0, 2));
        mloc1 = fmaxf(mloc1, __shfl_xor_sync(0xffffffffu, mloc1, 1));
        mloc1 = fmaxf(mloc1, __shfl_xor_sync(0xffffffffu, mloc1, 2));

        float mn0 = fmaxf(m0, mloc0);
        float mn1 = fmaxf(m1, mloc1);
        float sc0 = __expf(m0 - mn0);
        float sc1 = __expf(m1 - mn1);

        float ps0 = 0.f, ps1 = 0.f;
#pragma unroll
        for (int nt = 0; nt < 4; nt++) {
            float p0 = __expf(s[nt][0] - mn0);
            float p1 = __expf(s[nt][1] - mn0);
            float p2 = __expf(s[nt][2] - mn1);
            float p3 = __expf(s[nt][3] - mn1);
            ps0 += p0 + p1;
            ps1 += p2 + p3;
            float* d0 = &Pw[g * PP + nt * 8 + 2 * tig];
            d0[0] = f2tf(p0); d0[1] = f2tf(p1);
            float* d1 = &Pw[(g + 8) * PP + nt * 8 + 2 * tig];
            d1[0] = f2tf(p2); d1[1] = f2tf(p3);
        }
        ps0 += __shfl_xor_sync(0xffffffffu, ps0, 1);
        ps0 += __shfl_xor_sync(0xffffffffu, ps0, 2);
        ps1 += __shfl_xor_sync(0xffffffffu, ps1, 1);
        ps1 += __shfl_xor_sync(0xffffffffu, ps1, 2);

        l0 = l0 * sc0 + ps0;  m0 = mn0;
        l1 = l1 * sc1 + ps1;  m1 = mn1;

        __syncwarp();

        // ---- rescale O, then O += P @ V ----
#pragma unroll
        for (int nt = 0; nt < 16; nt++) {
            o[nt][0] *= sc0; o[nt][1] *= sc0;
            o[nt][2] *= sc1; o[nt][3] *= sc1;
        }

#pragma unroll
        for (int ks = 0; ks < 4; ks++) {
            const int kk = ks * 8;
            const float* ab = &Pw[g * PP + kk + tig];
            uint32_t a0 = ldu(ab);
            uint32_t a1 = ldu(ab + 8 * PP);
            uint32_t a2 = ldu(ab + 4);
            uint32_t a3 = ldu(ab + 8 * PP + 4);
#pragma unroll
            for (int nt = 0; nt < 16; nt++) {
                uint32_t b0 = ldu(&Vs[(kk + tig) * VP + nt * 8 + g]);
                uint32_t b1 = ldu(&Vs[(kk + tig + 4) * VP + nt * 8 + g]);
                mma8(o[nt][0], o[nt][1], o[nt][2], o[nt][3], a0, a1, a2, a3, b0, b1);
            }
        }

        __syncthreads();
        if (tc + 2 < nct) {
            issue_kv(tc + 2, Ks, Vs);   // reuse just-consumed buffers
            CP_WAIT(1);
            __syncthreads();
        } else if (tc + 1 < nct) {
            CP_WAIT(0);
            __syncthreads();
        }
    }

    // ---- write unnormalized partials ----
    const int pidx = r * MAXCH + c;
    float* baseO = &g_pO[(size_t)pidx * BMA * DK];
    const int row0 = warp * 16 + g;
    const int row1 = row0 + 8;
#pragma unroll
    for (int nt = 0; nt < 16; nt++) {
        int col = nt * 8 + 2 * tig;
        float2 w0; w0.x = o[nt][0]; w0.y = o[nt][1];
        float2 w1; w1.x = o[nt][2]; w1.y = o[nt][3];
        *reinterpret_cast<float2*>(&baseO[row0 * DK + col]) = w0;
        *reinterpret_cast<float2*>(&baseO[row1 * DK + col]) = w1;
    }
    if (tig == 0) {
        g_pm[pidx * BMA + row0] = m0;
        g_pm[pidx * BMA + row1] = m1;
        g_pl[pidx * BMA + row0] = l0;
        g_pl[pidx * BMA + row1] = l1;
    }
}

// ---------------------------------------------------------------------------
// Merge partials: grid 256 blocks, block (r, quarter) handles 16 rows x 128 d.
// ---------------------------------------------------------------------------
__global__ void __launch_bounds__(256) merge_kernel(float* __restrict__ out)
{
    __shared__ float s_w[MAXCH * 16];
    __shared__ float s_inv[16];

    const int r   = blockIdx.x >> 2;
    const int qq  = blockIdx.x & 3;
    const int nch = (r >> 3) + 1;
    const int t   = threadIdx.x;

    if (t < 16) {
        int row = qq * 16 + t;
        float mv[MAXCH], lv[MAXCH];
        float mx = -1e30f;
        for (int ch = 0; ch < nch; ch++) {
            mv[ch] = g_pm[(r * MAXCH + ch) * BMA + row];
            lv[ch] = g_pl[(r * MAXCH + ch) * BMA + row];
            mx = fmaxf(mx, mv[ch]);
        }
        float den = 0.f;
        for (int ch = 0; ch < nch; ch++) {
            float w = __expf(mv[ch] - mx);
            s_w[ch * 16 + t] = w;
            den += w * lv[ch];
        }
        s_inv[t] = 1.f / den;
    }
    __syncthreads();

#pragma unroll
    for (int i = 0; i < 8; i++) {
        int idx = t + i * 256;           // 2048 = 16 rows x 128
        int row16 = idx >> 7, d = idx & 127;
        int row = qq * 16 + row16;
        float acc = 0.f;
        for (int ch = 0; ch < nch; ch++)
            acc += s_w[ch * 16 + row16] *
                   g_pO[((size_t)(r * MAXCH + ch) * BMA + row) * DK + d];
        out[(r * BMA + row) * DK + d] = acc * s_inv[row16];
    }
}

// ---------------------------------------------------------------------------
extern "C" void kernel_launch(void* const* d_in, const int* in_sizes, int n_in,
                              void* d_out, int out_size)
{
    const float* q  = (const float*)d_in[0];
    const float* k  = (const float*)d_in[1];
    const float* v  = (const float*)d_in[2];
    const float* Wq = (const float*)d_in[3];
    const float* bq = (const float*)d_in[4];
    const float* Wk = (const float*)d_in[5];
    const float* bk = (const float*)d_in[6];
    const float* Wv = (const float*)d_in[7];
    const float* bv = (const float*)d_in[8];
    float* out = (float*)d_out;

    const int smem_proj = 2 * (PM * XP + PKC * WP) * sizeof(float);                 // 53248
    const int smem_attn = (64 * KP + 2 * 32 * KP + 2 * 32 * VP + 4 * 16 * PP) * sizeof(float); // 111616
    cudaFuncSetAttribute(proj_kernel, cudaFuncAttributeMaxDynamicSharedMemorySize, smem_proj);
    cudaFuncSetAttribute(attn_part_kernel, cudaFuncAttributeMaxDynamicSharedMemorySize, smem_attn);

    prep_kernel<<<dim3(128, 3), 256>>>(Wq, Wk, Wv);
    proj_kernel<<<dim3(SEQ / PM, 3), 256, smem_proj>>>(q, k, v, bq, bk, bv);
    attn_part_kernel<<<ABLOCKS, 128, smem_attn>>>();
    merge_kernel<<<NTA * 4, 256>>>(out);
}

// round 6
// speedup vs baseline: 6.5743x; 1.1564x over previous
#include <cuda_runtime.h>
#include <math.h>
#include <stdint.h>

#define SEQ 4096
#define DM  1024
#define DK  128

// ---- proj tiling ----
#define PM   64
#define PKC  32
#define PNCH (DM / PKC)   // 32 chunks
#define XP   36           // Xs stride
#define WP   136          // Ws stride (mod 32 = 8)

// ---- attention tiling ----
#define BMA   64
#define BNA   32
#define CHUNK 512
#define NTA   (SEQ / BMA)
#define MAXCH 8
#define ABLOCKS 288       // sum_{tier=1..8} 8*tier
#define KP  136           // K/V smem stride (mod 32 = 8: LDS.64 conflict-free)
#define PP  36
#define KST (32 * KP)     // 4352 floats per K/V buffer

// ---- scratch ----
__device__ float g_qp[SEQ * DK];   // d-permuted within 8-col groups
__device__ float g_kp[SEQ * DK];   // d-permuted within 8-col groups
__device__ float g_vp[SEQ * DK];   // plain layout
__device__ float g_pO[NTA * MAXCH * BMA * DK];
__device__ float g_pm[NTA * MAXCH * BMA];
__device__ float g_pl[NTA * MAXCH * BMA];

__device__ __forceinline__ float f2tf(float f) {
    uint32_t u;
    asm("cvt.rn.tf32.f32 %0, %1;" : "=r"(u) : "f"(f));
    return __uint_as_float(u);
}

__device__ __forceinline__ void mma8(float& d0, float& d1, float& d2, float& d3,
                                     uint32_t a0, uint32_t a1, uint32_t a2, uint32_t a3,
                                     uint32_t b0, uint32_t b1)
{
    asm volatile(
        "mma.sync.aligned.m16n8k8.row.col.f32.tf32.tf32.f32 "
        "{%0,%1,%2,%3}, {%4,%5,%6,%7}, {%8,%9}, {%0,%1,%2,%3};\n"
        : "+f"(d0), "+f"(d1), "+f"(d2), "+f"(d3)
        : "r"(a0), "r"(a1), "r"(a2), "r"(a3), "r"(b0), "r"(b1));
}

__device__ __forceinline__ uint32_t ldu(const float* p) { return __float_as_uint(*p); }
__device__ __forceinline__ uint32_t ldu_rn(const float* p) { return __float_as_uint(*p) + 0x1000u; }
__device__ __forceinline__ uint32_t bits_rn(float f) { return __float_as_uint(f); } // pre-rounded

__device__ __forceinline__ void cp16(void* dst_smem, const void* src_gmem) {
    uint32_t d = (uint32_t)__cvta_generic_to_shared(dst_smem);
    asm volatile("cp.async.cg.shared.global [%0], [%1], 16;" :: "r"(d), "l"(src_gmem));
}
#define CP_COMMIT() asm volatile("cp.async.commit_group;")
#define CP_WAIT(n)  asm volatile("cp.async.wait_group %0;" :: "n"(n))

// ---------------------------------------------------------------------------
// Projection: OUT = round_tf32((X @ W + b) * osc). 256 thr, tile 64 x 128.
// 3-stage cp.async pipeline, one sync per chunk. W rounded at frag load.
// q/k outputs stored with d-permutation p(j)=2(j&3)+(j>>2) within 8-groups.
// ---------------------------------------------------------------------------
__global__ void __launch_bounds__(256, 2) proj_kernel(
    const float* __restrict__ q, const float* __restrict__ k, const float* __restrict__ v,
    const float* __restrict__ Wq, const float* __restrict__ bq,
    const float* __restrict__ Wk, const float* __restrict__ bk,
    const float* __restrict__ Wv, const float* __restrict__ bv)
{
    extern __shared__ float psm[];
    float* Xb = psm;                   // 3 x 64 x 36
    float* Wb = psm + 3 * PM * XP;     // 3 x 32 x 136

    const int which = blockIdx.y;
    const float* X = (which == 0) ? q  : (which == 1) ? k  : v;
    const float* W = (which == 0) ? Wq : (which == 1) ? Wk : Wv;
    const float* B = (which == 0) ? bq : (which == 1) ? bk : bv;
    float* OUT     = (which == 0) ? g_qp : (which == 1) ? g_kp : g_vp;
    const float osc = (which == 0) ? 0.08838834764831845f : 1.0f;

    const int t    = threadIdx.x;
    const int warp = t >> 5;
    const int lane = t & 31;
    const int wr   = warp >> 2;
    const int wc   = warp & 3;
    const int g    = lane >> 2;
    const int tig  = lane & 3;
    const int r0   = blockIdx.x * PM;

    auto issue = [&](int kc) {
        const int k0 = kc * PKC;
        float* Xs = Xb + (kc % 3) * PM * XP;
        float* Ws = Wb + (kc % 3) * PKC * WP;
#pragma unroll
        for (int i = 0; i < 2; i++) {
            int idx = t + i * 256;
            int row = idx >> 3, c4 = idx & 7;
            cp16(&Xs[row * XP + c4 * 4], &X[(r0 + row) * DM + k0 + c4 * 4]);
        }
#pragma unroll
        for (int i = 0; i < 4; i++) {
            int idx = t + i * 256;
            int row = idx >> 5, c4 = idx & 31;
            cp16(&Ws[row * WP + c4 * 4], &W[(k0 + row) * DK + c4 * 4]);
        }
        CP_COMMIT();
    };

    float acc[8][4];
#pragma unroll
    for (int i = 0; i < 8; i++)
#pragma unroll
        for (int j = 0; j < 4; j++) acc[i][j] = 0.f;

    issue(0);
    issue(1);

    for (int kc = 0; kc < PNCH; kc++) {
        if (kc + 1 < PNCH) { CP_WAIT(1); } else { CP_WAIT(0); }
        __syncthreads();
        if (kc + 2 < PNCH) issue(kc + 2);

        const float* Xs = Xb + (kc % 3) * PM * XP;
        const float* Ws = Wb + (kc % 3) * PKC * WP;

#pragma unroll
        for (int ks = 0; ks < 4; ks++) {
            const int kk = ks * 8;
            uint32_t a[2][4];
#pragma unroll
            for (int mf = 0; mf < 2; mf++) {
                const float* ab = &Xs[(wr * 32 + mf * 16 + g) * XP + kk + tig];
                a[mf][0] = ldu_rn(ab);
                a[mf][1] = ldu_rn(ab + 8 * XP);
                a[mf][2] = ldu_rn(ab + 4);
                a[mf][3] = ldu_rn(ab + 8 * XP + 4);
            }
            uint32_t b[4][2];
#pragma unroll
            for (int nf = 0; nf < 4; nf++) {
                b[nf][0] = ldu_rn(&Ws[(kk + tig) * WP + wc * 32 + nf * 8 + g]);
                b[nf][1] = ldu_rn(&Ws[(kk + tig + 4) * WP + wc * 32 + nf * 8 + g]);
            }
#pragma unroll
            for (int mf = 0; mf < 2; mf++)
#pragma unroll
                for (int nf = 0; nf < 4; nf++)
                    mma8(acc[mf * 4 + nf][0], acc[mf * 4 + nf][1],
                         acc[mf * 4 + nf][2], acc[mf * 4 + nf][3],
                         a[mf][0], a[mf][1], a[mf][2], a[mf][3],
                         b[nf][0], b[nf][1]);
        }
    }

    // epilogue
    const int j0 = 2 * tig, j1 = j0 + 1;
    const int p0 = 2 * (j0 & 3) + (j0 >> 2);
    const int p1 = 2 * (j1 & 3) + (j1 >> 2);
#pragma unroll
    for (int mf = 0; mf < 2; mf++) {
        const int row0 = r0 + wr * 32 + mf * 16 + g;
        const int row1 = row0 + 8;
#pragma unroll
        for (int nf = 0; nf < 4; nf++) {
            int colb = wc * 32 + nf * 8;
            float2 bb = *reinterpret_cast<const float2*>(&B[colb + j0]);
            float v00 = f2tf((acc[mf * 4 + nf][0] + bb.x) * osc);
            float v01 = f2tf((acc[mf * 4 + nf][1] + bb.y) * osc);
            float v10 = f2tf((acc[mf * 4 + nf][2] + bb.x) * osc);
            float v11 = f2tf((acc[mf * 4 + nf][3] + bb.y) * osc);
            if (which == 2) {   // V plain layout, float2
                float2 o0; o0.x = v00; o0.y = v01;
                float2 o1; o1.x = v10; o1.y = v11;
                *reinterpret_cast<float2*>(&OUT[row0 * DK + colb + j0]) = o0;
                *reinterpret_cast<float2*>(&OUT[row1 * DK + colb + j0]) = o1;
            } else {            // Q/K permuted, scalar
                OUT[row0 * DK + colb + p0] = v00;
                OUT[row0 * DK + colb + p1] = v01;
                OUT[row1 * DK + colb + p0] = v10;
                OUT[row1 * DK + colb + p1] = v11;
            }
        }
    }
}

// ---------------------------------------------------------------------------
// Split-KV causal flash attention partials. Q/K d-permuted (float2 frags),
// 3-stage cp.async K/V pipeline, one sync per tile, Q frags cached in regs.
// ---------------------------------------------------------------------------
__global__ void __launch_bounds__(128, 2) attn_part_kernel()
{
    extern __shared__ float sm[];
    float* Kb = sm;                 // 3 x 32 x 136
    float* Vb = sm + 3 * KST;       // 3 x 32 x 136
    float* Ps = sm + 6 * KST;       // 4 x 16 x 36

    const int t    = threadIdx.x;
    const int warp = t >> 5;
    const int lane = t & 31;
    const int g    = lane >> 2;
    const int tig  = lane & 3;
    float* Pw = Ps + warp * (16 * PP);

    // heavy-first decode: tile r has (r/8)+1 chunks
    int Bd = ABLOCKS - 1 - (int)blockIdx.x;
    int tier = 1, rem = Bd;
    while (rem >= 8 * tier) { rem -= 8 * tier; tier++; }
    const int r = (tier - 1) * 8 + rem / tier;
    const int c = rem % tier;

    const int rbase  = r * BMA;
    const int c0base = c * CHUNK;
    const int colend = min(c0base + CHUNK, rbase + BMA);
    const int nct    = (colend - c0base) / BNA;   // >= 2 always

    auto issue_kv = [&](int tc) {
        const int c0 = c0base + tc * BNA;
        float* Kd = Kb + (tc % 3) * KST;
        float* Vd = Vb + ((tc + 2) % 3) * KST;
#pragma unroll
        for (int i = 0; i < 8; i++) {
            int idx = t + i * 128;
            int row = idx >> 5, c4 = idx & 31;
            cp16(&Kd[row * KP + c4 * 4], &g_kp[(c0 + row) * DK + c4 * 4]);
            cp16(&Vd[row * KP + c4 * 4], &g_vp[(c0 + row) * DK + c4 * 4]);
        }
        CP_COMMIT();
    };

    // group 1: Q -> V buffers 0,1 (64 rows)
#pragma unroll
    for (int i = 0; i < 16; i++) {
        int idx = t + i * 128;
        int row = idx >> 5, c4 = idx & 31;
        cp16(&Vb[(row >> 5) * KST + (row & 31) * KP + c4 * 4],
             &g_qp[(rbase + row) * DK + c4 * 4]);
    }
    CP_COMMIT();
    // group 2: tile 0 -> K0, V2
    issue_kv(0);
    CP_WAIT(1);           // Q landed
    __syncthreads();

    // cache Q A-fragments (permuted layout -> float2)
    uint32_t qf[16][4];
    {
        const float* Qsrc = Vb + (warp >> 1) * KST;
        const int row_l = (warp & 1) * 16 + g;
#pragma unroll
        for (int ks = 0; ks < 16; ks++) {
            float2 qa = *reinterpret_cast<const float2*>(&Qsrc[row_l * KP + ks * 8 + 2 * tig]);
            float2 qb = *reinterpret_cast<const float2*>(&Qsrc[(row_l + 8) * KP + ks * 8 + 2 * tig]);
            qf[ks][0] = bits_rn(qa.x);   // (row,   k)
            qf[ks][1] = bits_rn(qb.x);   // (row+8, k)
            qf[ks][2] = bits_rn(qa.y);   // (row,   k+4)
            qf[ks][3] = bits_rn(qb.y);   // (row+8, k+4)
        }
    }
    __syncthreads();      // V0/V1 free
    issue_kv(1);          // tile 1 -> K1, V0

    float o[16][4];
#pragma unroll
    for (int nt = 0; nt < 16; nt++)
#pragma unroll
        for (int j = 0; j < 4; j++) o[nt][j] = 0.f;

    float m0 = -1e30f, m1 = -1e30f, l0 = 0.f, l1 = 0.f;
    const int grow0 = rbase + warp * 16 + g;
    const int grow1 = grow0 + 8;

    for (int tc = 0; tc < nct; tc++) {
        const int c0 = c0base + tc * BNA;
        if (tc + 1 < nct) { CP_WAIT(1); } else { CP_WAIT(0); }
        __syncthreads();
        if (tc + 2 < nct) issue_kv(tc + 2);

        const float* Ks = Kb + (tc % 3) * KST;
        const float* Vs = Vb + ((tc + 2) % 3) * KST;

        // ---- S = Q K^T ----
        float s[4][4];
#pragma unroll
        for (int nt = 0; nt < 4; nt++)
#pragma unroll
            for (int j = 0; j < 4; j++) s[nt][j] = 0.f;

#pragma unroll
        for (int ks = 0; ks < 16; ks++) {
            const int kk = ks * 8;
#pragma unroll
            for (int nt = 0; nt < 4; nt++) {
                float2 kv = *reinterpret_cast<const float2*>(&Ks[(nt * 8 + g) * KP + kk + 2 * tig]);
                mma8(s[nt][0], s[nt][1], s[nt][2], s[nt][3],
                     qf[ks][0], qf[ks][1], qf[ks][2], qf[ks][3],
                     bits_rn(kv.x), bits_rn(kv.y));
            }
        }

        // ---- causal mask + online softmax ----
        float mloc0 = -1e30f, mloc1 = -1e30f;
#pragma unroll
        for (int nt = 0; nt < 4; nt++) {
            int colb = c0 + nt * 8 + 2 * tig;
            float x0 = (colb     <= grow0) ? s[nt][0] : -1e30f;
            float x1 = (colb + 1 <= grow0) ? s[nt][1] : -1e30f;
            float x2 = (colb     <= grow1) ? s[nt][2] : -1e30f;
            float x3 = (colb + 1 <= grow1) ? s[nt][3] : -1e30f;
            s[nt][0] = x0; s[nt][1] = x1; s[nt][2] = x2; s[nt][3] = x3;
            mloc0 = fmaxf(mloc0, fmaxf(x0, x1));
            mloc1 = fmaxf(mloc1, fmaxf(x2, x3));
        }
        mloc0 = fmaxf(mloc0, __shfl_xor_sync(0xffffffffu, mloc0, 1));
        mloc0 = fmaxf(mloc0, __shfl_xor_sync(0xffffffffu, mloc0, 2));
        mloc1 = fmaxf(mloc1, __shfl_xor_sync(0xffffffffu, mloc1, 1));
        mloc1 = fmaxf(mloc1, __shfl_xor_sync(0xffffffffu, mloc1, 2));

        float mn0 = fmaxf(m0, mloc0);
        float mn1 = fmaxf(m1, mloc1);
        float sc0 = __expf(m0 - mn0);
        float sc1 = __expf(m1 - mn1);

        float ps0 = 0.f, ps1 = 0.f;
#pragma unroll
        for (int nt = 0; nt < 4; nt++) {
            float p0 = __expf(s[nt][0] - mn0);
            float p1 = __expf(s[nt][1] - mn0);
            float p2 = __expf(s[nt][2] - mn1);
            float p3 = __expf(s[nt][3] - mn1);
            ps0 += p0 + p1;
            ps1 += p2 + p3;
            float* d0 = &Pw[g * PP + nt * 8 + 2 * tig];
            d0[0] = f2tf(p0); d0[1] = f2tf(p1);
            float* d1 = &Pw[(g + 8) * PP + nt * 8 + 2 * tig];
            d1[0] = f2tf(p2); d1[1] = f2tf(p3);
        }
        ps0 += __shfl_xor_sync(0xffffffffu, ps0, 1);
        ps0 += __shfl_xor_sync(0xffffffffu, ps0, 2);
        ps1 += __shfl_xor_sync(0xffffffffu, ps1, 1);
        ps1 += __shfl_xor_sync(0xffffffffu, ps1, 2);

        l0 = l0 * sc0 + ps0;  m0 = mn0;
        l1 = l1 * sc1 + ps1;  m1 = mn1;

        __syncwarp();

        // ---- rescale O, then O += P @ V ----
#pragma unroll
        for (int nt = 0; nt < 16; nt++) {
            o[nt][0] *= sc0; o[nt][1] *= sc0;
            o[nt][2] *= sc1; o[nt][3] *= sc1;
        }

#pragma unroll
        for (int ks = 0; ks < 4; ks++) {
            const int kk = ks * 8;
            const float* ab = &Pw[g * PP + kk + tig];
            uint32_t a0 = ldu(ab);
            uint32_t a1 = ldu(ab + 8 * PP);
            uint32_t a2 = ldu(ab + 4);
            uint32_t a3 = ldu(ab + 8 * PP + 4);
#pragma unroll
            for (int nt = 0; nt < 16; nt++) {
                uint32_t b0 = ldu(&Vs[(kk + tig) * KP + nt * 8 + g]);
                uint32_t b1 = ldu(&Vs[(kk + tig + 4) * KP + nt * 8 + g]);
                mma8(o[nt][0], o[nt][1], o[nt][2], o[nt][3], a0, a1, a2, a3, b0, b1);
            }
        }
    }

    // ---- write unnormalized partials ----
    const int pidx = r * MAXCH + c;
    float* baseO = &g_pO[(size_t)pidx * BMA * DK];
    const int row0 = warp * 16 + g;
    const int row1 = row0 + 8;
#pragma unroll
    for (int nt = 0; nt < 16; nt++) {
        int col = nt * 8 + 2 * tig;
        float2 w0; w0.x = o[nt][0]; w0.y = o[nt][1];
        float2 w1; w1.x = o[nt][2]; w1.y = o[nt][3];
        *reinterpret_cast<float2*>(&baseO[row0 * DK + col]) = w0;
        *reinterpret_cast<float2*>(&baseO[row1 * DK + col]) = w1;
    }
    if (tig == 0) {
        g_pm[pidx * BMA + row0] = m0;
        g_pm[pidx * BMA + row1] = m1;
        g_pl[pidx * BMA + row0] = l0;
        g_pl[pidx * BMA + row1] = l1;
    }
}

// ---------------------------------------------------------------------------
// Merge: 512 blocks, block (r, oct) handles 8 rows x 128 d. float4, MLP 16.
// ---------------------------------------------------------------------------
__global__ void __launch_bounds__(128) merge_kernel(float* __restrict__ out)
{
    __shared__ float s_m[8 * MAXCH];
    __shared__ float s_l[8 * MAXCH];
    __shared__ float s_w[8 * MAXCH];
    __shared__ float s_inv[8];

    const int r   = blockIdx.x >> 3;
    const int oct = blockIdx.x & 7;
    const int nch = (r >> 3) + 1;
    const int t   = threadIdx.x;

    if (t < 64) {
        int row8 = t >> 3, ch = t & 7;
        if (ch < nch) {
            s_m[t] = g_pm[(r * MAXCH + ch) * BMA + oct * 8 + row8];
            s_l[t] = g_pl[(r * MAXCH + ch) * BMA + oct * 8 + row8];
        } else {
            s_m[t] = -1e30f; s_l[t] = 0.f;
        }
    }
    __syncthreads();

    if (t < 8) {
        float mx = -1e30f;
#pragma unroll
        for (int ch = 0; ch < MAXCH; ch++) mx = fmaxf(mx, s_m[t * 8 + ch]);
        float den = 0.f;
#pragma unroll
        for (int ch = 0; ch < MAXCH; ch++) {
            float w = __expf(s_m[t * 8 + ch] - mx);
            s_w[t * 8 + ch] = w;
            den += w * s_l[t * 8 + ch];
        }
        s_inv[t] = 1.f / den;
    }
    __syncthreads();

#pragma unroll
    for (int i = 0; i < 2; i++) {
        int f4 = t + i * 128;            // < 256 = 8 rows x 32 float4
        int row8 = f4 >> 5, d4 = f4 & 31;
        int growl = oct * 8 + row8;
        float4 acc; acc.x = acc.y = acc.z = acc.w = 0.f;
#pragma unroll
        for (int ch = 0; ch < MAXCH; ch++) {
            if (ch < nch) {
                const float4* src = reinterpret_cast<const float4*>(
                    &g_pO[((size_t)(r * MAXCH + ch) * BMA + growl) * DK]);
                float4 p = src[d4];
                float w = s_w[row8 * 8 + ch];
                acc.x += w * p.x; acc.y += w * p.y;
                acc.z += w * p.z; acc.w += w * p.w;
            }
        }
        float inv = s_inv[row8];
        acc.x *= inv; acc.y *= inv; acc.z *= inv; acc.w *= inv;
        reinterpret_cast<float4*>(&out[(r * BMA + growl) * DK])[d4] = acc;
    }
}

// ---------------------------------------------------------------------------
extern "C" void kernel_launch(void* const* d_in, const int* in_sizes, int n_in,
                              void* d_out, int out_size)
{
    const float* q  = (const float*)d_in[0];
    const float* k  = (const float*)d_in[1];
    const float* v  = (const float*)d_in[2];
    const float* Wq = (const float*)d_in[3];
    const float* bq = (const float*)d_in[4];
    const float* Wk = (const float*)d_in[5];
    const float* bk = (const float*)d_in[6];
    const float* Wv = (const float*)d_in[7];
    const float* bv = (const float*)d_in[8];
    float* out = (float*)d_out;

    const int smem_proj = 3 * (PM * XP + PKC * WP) * sizeof(float);        // 79872
    const int smem_attn = (6 * KST + 4 * 16 * PP) * sizeof(float);         // 113664
    cudaFuncSetAttribute(proj_kernel, cudaFuncAttributeMaxDynamicSharedMemorySize, smem_proj);
    cudaFuncSetAttribute(attn_part_kernel, cudaFuncAttributeMaxDynamicSharedMemorySize, smem_attn);

    proj_kernel<<<dim3(SEQ / PM, 3), 256, smem_proj>>>(q, k, v, Wq, bq, Wk, bk, Wv, bv);
    attn_part_kernel<<<ABLOCKS, 128, smem_attn>>>();
    merge_kernel<<<NTA * 8, 128>>>(out);
}